// round 2
// baseline (speedup 1.0000x reference)
#include <cuda_runtime.h>

#define BB   32
#define NN   16384
#define DD   128
#define IDM  64
#define NCLS 10

// Scratch (device globals — no allocation allowed)
__device__ float g_scores[BB * NN];
__device__ float g_u[BB * DD];
__device__ float g_C[BB];

__device__ __forceinline__ float gelu_exact(float x) {
    return 0.5f * x * (1.0f + erff(x * 0.7071067811865475f));
}

// ---------------------------------------------------------------------------
// Kernel 1: per-batch precompute. 32 blocks x 128 threads.
// h_query = MLP(x_query); q = h_query@wqp+bqp; t = wkp@q; u = wx2@t;
// C = bx2.t + bkp.q
// ---------------------------------------------------------------------------
__global__ void __launch_bounds__(128) k1_precompute(
    const float* __restrict__ xq_all,
    const float* __restrict__ wq1, const float* __restrict__ bq1,
    const float* __restrict__ wq2, const float* __restrict__ bq2,
    const float* __restrict__ wqp, const float* __restrict__ bqp,
    const float* __restrict__ wkp, const float* __restrict__ bkp,
    const float* __restrict__ wx2, const float* __restrict__ bx2)
{
    __shared__ float s0[DD];
    __shared__ float s1[DD];
    __shared__ float red[128];
    const int b = blockIdx.x;
    const int i = threadIdx.x;
    const float xq = xq_all[b];

    // layer 1 of query MLP (fan_in = 1)
    s0[i] = gelu_exact(xq * wq1[i] + bq1[i]);
    __syncthreads();
    // h_query
    float acc = bq2[i];
    for (int k = 0; k < DD; k++) acc += s0[k] * wq2[k * DD + i];
    s1[i] = acc;
    __syncthreads();
    // q
    acc = bqp[i];
    for (int k = 0; k < DD; k++) acc += s1[k] * wqp[k * DD + i];
    s0[i] = acc;              // s0 = q
    __syncthreads();
    // t_i = sum_j wkp[i,j] * q[j]
    acc = 0.f;
    for (int j = 0; j < DD; j++) acc += wkp[i * DD + j] * s0[j];
    s1[i] = acc;              // s1 = t
    __syncthreads();
    // u_i = sum_j wx2[i,j] * t[j]
    acc = 0.f;
    for (int j = 0; j < DD; j++) acc += wx2[i * DD + j] * s1[j];
    g_u[b * DD + i] = acc;
    // C = bx2.t + bkp.q
    red[i] = bx2[i] * s1[i] + bkp[i] * s0[i];
    __syncthreads();
    for (int s = 64; s > 0; s >>= 1) {
        if (i < s) red[i] += red[i + s];
        __syncthreads();
    }
    if (i == 0) g_C[b] = red[0];
}

// ---------------------------------------------------------------------------
// Kernel 2 (dominant): score_n = scale*(gelu(x_n@wx1+bx1) . u + C)
// Grid (NN/256, BB), 256 threads, 1 item/thread, f32x2 packed FMA.
// ---------------------------------------------------------------------------
__global__ void __launch_bounds__(256) k2_scores(
    const float* __restrict__ x_items,
    const float* __restrict__ wx1,
    const float* __restrict__ bx1)
{
    __shared__ __align__(16) float W1s[IDM * DD];   // 32 KB, [k*128 + i]
    __shared__ __align__(16) float b1s[DD];
    __shared__ float us[DD];
    __shared__ float Cs;

    const int tid = threadIdx.x;
    const int b   = blockIdx.y;

    for (int idx = tid; idx < IDM * DD; idx += 256) W1s[idx] = wx1[idx];
    if (tid < DD) { b1s[tid] = bx1[tid]; us[tid] = g_u[b * DD + tid]; }
    if (tid == 0) Cs = g_C[b];
    __syncthreads();

    const int n = blockIdx.x * 256 + tid;
    const float4* xr =
        reinterpret_cast<const float4*>(x_items + ((size_t)b * NN + (size_t)n) * IDM);
    float x[IDM];
#pragma unroll
    for (int c = 0; c < IDM / 4; c++) {
        float4 v = xr[c];
        x[4 * c + 0] = v.x; x[4 * c + 1] = v.y;
        x[4 * c + 2] = v.z; x[4 * c + 3] = v.w;
    }

    float score = 0.0f;
#pragma unroll 1
    for (int ib = 0; ib < DD; ib += 16) {
        unsigned long long acc[8];
#pragma unroll
        for (int p = 0; p < 8; p++)
            acc[p] = *reinterpret_cast<const unsigned long long*>(&b1s[ib + 2 * p]);

#pragma unroll
        for (int k = 0; k < IDM; k++) {
            unsigned long long xp2;
            asm("mov.b64 %0, {%1, %1};" : "=l"(xp2) : "f"(x[k]));
            const longlong2* wr =
                reinterpret_cast<const longlong2*>(&W1s[k * DD + ib]);
            longlong2 wa = wr[0];
            longlong2 wb = wr[1];
            longlong2 wc = wr[2];
            longlong2 wd = wr[3];
            asm("fma.rn.f32x2 %0, %1, %2, %0;" : "+l"(acc[0]) : "l"(xp2), "l"((unsigned long long)wa.x));
            asm("fma.rn.f32x2 %0, %1, %2, %0;" : "+l"(acc[1]) : "l"(xp2), "l"((unsigned long long)wa.y));
            asm("fma.rn.f32x2 %0, %1, %2, %0;" : "+l"(acc[2]) : "l"(xp2), "l"((unsigned long long)wb.x));
            asm("fma.rn.f32x2 %0, %1, %2, %0;" : "+l"(acc[3]) : "l"(xp2), "l"((unsigned long long)wb.y));
            asm("fma.rn.f32x2 %0, %1, %2, %0;" : "+l"(acc[4]) : "l"(xp2), "l"((unsigned long long)wc.x));
            asm("fma.rn.f32x2 %0, %1, %2, %0;" : "+l"(acc[5]) : "l"(xp2), "l"((unsigned long long)wc.y));
            asm("fma.rn.f32x2 %0, %1, %2, %0;" : "+l"(acc[6]) : "l"(xp2), "l"((unsigned long long)wd.x));
            asm("fma.rn.f32x2 %0, %1, %2, %0;" : "+l"(acc[7]) : "l"(xp2), "l"((unsigned long long)wd.y));
        }

#pragma unroll
        for (int p = 0; p < 8; p++) {
            float lo, hi;
            asm("mov.b64 {%0, %1}, %2;" : "=f"(lo), "=f"(hi) : "l"(acc[p]));
            score += gelu_exact(lo) * us[ib + 2 * p];
            score += gelu_exact(hi) * us[ib + 2 * p + 1];
        }
    }

    // scale = 128^-0.5
    g_scores[b * NN + n] = 0.08838834764831845f * (score + Cs);
}

// ---------------------------------------------------------------------------
// Kernel 3: sparsemax (bisection + exact refine) + sparse readout + head MLP.
// 32 blocks (one per batch) x 512 threads.
// ---------------------------------------------------------------------------
__global__ void __launch_bounds__(512) k3_sparsemax_out(
    const float* __restrict__ x_items,
    const float* __restrict__ wx1, const float* __restrict__ bx1,
    const float* __restrict__ wx2, const float* __restrict__ bx2,
    const float* __restrict__ wvp, const float* __restrict__ bvp,
    const float* __restrict__ wp1, const float* __restrict__ bp1,
    const float* __restrict__ wp2, const float* __restrict__ bp2,
    float* __restrict__ out)
{
    __shared__ float rpart[16];
    __shared__ float rpart2[16];
    __shared__ float accg[DD];
    __shared__ float buf1[DD];
    __shared__ float buf2[DD];

    const int tid  = threadIdx.x;
    const int b    = blockIdx.x;
    const int lane = tid & 31;
    const int wid  = tid >> 5;
    const float* sc = g_scores + b * NN;

    float z[32];
#pragma unroll
    for (int j = 0; j < 32; j++) z[j] = sc[tid + j * 512];

    // ---- block max ----
    float m = z[0];
#pragma unroll
    for (int j = 1; j < 32; j++) m = fmaxf(m, z[j]);
#pragma unroll
    for (int o = 16; o > 0; o >>= 1) m = fmaxf(m, __shfl_xor_sync(0xffffffffu, m, o));
    if (lane == 0) rpart[wid] = m;
    __syncthreads();
    float zmax = rpart[0];
#pragma unroll
    for (int j = 1; j < 16; j++) zmax = fmaxf(zmax, rpart[j]);

    // ---- bisection: root of f(tau) = sum relu(z - tau) - 1, tau in [zmax-1, zmax]
    float lo = zmax - 1.0f, hi = zmax;
    for (int it = 0; it < 34; it++) {
        float mid = 0.5f * (lo + hi);
        float s = 0.f;
#pragma unroll
        for (int j = 0; j < 32; j++) s += fmaxf(z[j] - mid, 0.f);
#pragma unroll
        for (int o = 16; o > 0; o >>= 1) s += __shfl_xor_sync(0xffffffffu, s, o);
        __syncthreads();
        if (lane == 0) rpart[wid] = s;
        __syncthreads();
        float f = 0.f;
#pragma unroll
        for (int j = 0; j < 16; j++) f += rpart[j];   // same order in all threads
        if (f > 1.0f) lo = mid; else hi = mid;
    }
    const float tau0 = 0.5f * (lo + hi);

    // ---- exact refine: support {z > tau0}, tau = (S - 1)/k
    float ssum = 0.f, scnt = 0.f;
#pragma unroll
    for (int j = 0; j < 32; j++) {
        if (z[j] > tau0) { ssum += z[j]; scnt += 1.f; }
    }
#pragma unroll
    for (int o = 16; o > 0; o >>= 1) {
        ssum += __shfl_xor_sync(0xffffffffu, ssum, o);
        scnt += __shfl_xor_sync(0xffffffffu, scnt, o);
    }
    __syncthreads();
    if (lane == 0) { rpart[wid] = ssum; rpart2[wid] = scnt; }
    __syncthreads();
    float S = 0.f, K = 0.f;
#pragma unroll
    for (int j = 0; j < 16; j++) { S += rpart[j]; K += rpart2[j]; }
    const float tau = (S - 1.0f) / K;

    // ---- sparse accumulation: Gbar = sum_n attn_n * gelu(x_n@wx1+bx1)
    if (tid < DD) accg[tid] = 0.f;
    __syncthreads();

    for (int base = wid * 32; base < NN; base += 512) {
        float zz = sc[base + lane];
        unsigned msk = __ballot_sync(0xffffffffu, zz > tau0);
        while (msk) {
            int j = __ffs(msk) - 1;
            msk &= msk - 1;
            float w = fmaxf(__shfl_sync(0xffffffffu, zz, j) - tau, 0.f);
            const float* xr = x_items + ((size_t)b * NN + (size_t)(base + j)) * IDM;
            float x0 = xr[2 * lane], x1 = xr[2 * lane + 1];
            float a0 = bx1[lane];
            float a1 = bx1[lane + 32];
            float a2 = bx1[lane + 64];
            float a3 = bx1[lane + 96];
#pragma unroll
            for (int k = 0; k < IDM; k++) {
                float xv = __shfl_sync(0xffffffffu, (k & 1) ? x1 : x0, k >> 1);
                a0 += xv * wx1[k * DD + lane];
                a1 += xv * wx1[k * DD + lane + 32];
                a2 += xv * wx1[k * DD + lane + 64];
                a3 += xv * wx1[k * DD + lane + 96];
            }
            atomicAdd(&accg[lane],      w * gelu_exact(a0));
            atomicAdd(&accg[lane + 32], w * gelu_exact(a1));
            atomicAdd(&accg[lane + 64], w * gelu_exact(a2));
            atomicAdd(&accg[lane + 96], w * gelu_exact(a3));
        }
    }
    __syncthreads();

    // Hbar = Gbar@wx2 + bx2
    if (tid < DD) {
        float hv = bx2[tid];
        for (int k = 0; k < DD; k++) hv += accg[k] * wx2[k * DD + tid];
        buf1[tid] = hv;
    }
    __syncthreads();
    // zvec = Hbar@wvp + bvp     (sum attn = 1)
    if (tid < DD) {
        float zv = bvp[tid];
        for (int k = 0; k < DD; k++) zv += buf1[k] * wvp[k * DD + tid];
        buf2[tid] = zv;
    }
    __syncthreads();
    // p1 = gelu(zvec@wp1 + bp1)
    if (tid < DD) {
        float pv = bp1[tid];
        for (int k = 0; k < DD; k++) pv += buf2[k] * wp1[k * DD + tid];
        buf1[tid] = gelu_exact(pv);
    }
    __syncthreads();
    // out = p1@wp2 + bp2
    if (tid < NCLS) {
        float o = bp2[tid];
        for (int k = 0; k < DD; k++) o += buf1[k] * wp2[k * NCLS + tid];
        out[b * NCLS + tid] = o;
    }
}

// ---------------------------------------------------------------------------
extern "C" void kernel_launch(void* const* d_in, const int* in_sizes, int n_in,
                              void* d_out, int out_size)
{
    const float* x_items = (const float*)d_in[0];
    const float* x_query = (const float*)d_in[1];
    const float* wx1 = (const float*)d_in[2];
    const float* bx1 = (const float*)d_in[3];
    const float* wx2 = (const float*)d_in[4];
    const float* bx2 = (const float*)d_in[5];
    const float* wq1 = (const float*)d_in[6];
    const float* bq1 = (const float*)d_in[7];
    const float* wq2 = (const float*)d_in[8];
    const float* bq2 = (const float*)d_in[9];
    const float* wqp = (const float*)d_in[10];
    const float* bqp = (const float*)d_in[11];
    const float* wkp = (const float*)d_in[12];
    const float* bkp = (const float*)d_in[13];
    const float* wvp = (const float*)d_in[14];
    const float* bvp = (const float*)d_in[15];
    const float* wp1 = (const float*)d_in[16];
    const float* bp1 = (const float*)d_in[17];
    const float* wp2 = (const float*)d_in[18];
    const float* bp2 = (const float*)d_in[19];
    float* out = (float*)d_out;

    k1_precompute<<<BB, 128>>>(x_query, wq1, bq1, wq2, bq2, wqp, bqp,
                               wkp, bkp, wx2, bx2);

    dim3 g2(NN / 256, BB);
    k2_scores<<<g2, 256>>>(x_items, wx1, bx1);

    k3_sparsemax_out<<<BB, 512>>>(x_items, wx1, bx1, wx2, bx2,
                                  wvp, bvp, wp1, bp1, wp2, bp2, out);
}

// round 5
// speedup vs baseline: 1.2335x; 1.2335x over previous
#include <cuda_runtime.h>
#include <cuda_bf16.h>
#include <cstdint>

#define BB   32
#define NN   16384
#define DD   128
#define IDM  64
#define NCLS 10

// ---------------------------------------------------------------------------
// Scratch (device globals — no allocation allowed)
// ---------------------------------------------------------------------------
__device__ float g_scores[BB * NN];
__device__ float g_u[BB * DD];
__device__ float g_C[BB];
__device__ __align__(16) __nv_bfloat16 g_wt_hi[DD * IDM];  // [n*64 + k]
__device__ __align__(16) __nv_bfloat16 g_wt_lo[DD * IDM];

__device__ __forceinline__ float gelu_exact(float x) {
    return 0.5f * x * (1.0f + erff(x * 0.7071067811865475f));
}

// m16n8k16 row.col bf16 MMA with f32 accumulate (arch-stable, sm_80+)
__device__ __forceinline__ void mma16816(float* c, const uint32_t* a,
                                         uint32_t b0, uint32_t b1) {
    asm volatile(
        "mma.sync.aligned.m16n8k16.row.col.f32.bf16.bf16.f32 "
        "{%0,%1,%2,%3}, {%4,%5,%6,%7}, {%8,%9}, {%0,%1,%2,%3};"
        : "+f"(c[0]), "+f"(c[1]), "+f"(c[2]), "+f"(c[3])
        : "r"(a[0]), "r"(a[1]), "r"(a[2]), "r"(a[3]), "r"(b0), "r"(b1));
}

// ---------------------------------------------------------------------------
// Kernel 0: weight prep — transpose wx1 to [n,k] and split into bf16 hi/lo.
// ---------------------------------------------------------------------------
__global__ void __launch_bounds__(256) k0_prep_weights(const float* __restrict__ wx1)
{
    int idx = blockIdx.x * 256 + threadIdx.x;   // idx = k*128 + n
    if (idx >= IDM * DD) return;
    int k = idx >> 7;
    int n = idx & 127;
    float w = wx1[idx];
    __nv_bfloat16 hi = __float2bfloat16(w);
    __nv_bfloat16 lo = __float2bfloat16(w - __bfloat162float(hi));
    g_wt_hi[n * IDM + k] = hi;
    g_wt_lo[n * IDM + k] = lo;
}

// ---------------------------------------------------------------------------
// Kernel 1: per-batch precompute (query MLP chain, u, C). 32 blocks x 128.
// ---------------------------------------------------------------------------
__global__ void __launch_bounds__(128) k1_precompute(
    const float* __restrict__ xq_all,
    const float* __restrict__ wq1, const float* __restrict__ bq1,
    const float* __restrict__ wq2, const float* __restrict__ bq2,
    const float* __restrict__ wqp, const float* __restrict__ bqp,
    const float* __restrict__ wkp, const float* __restrict__ bkp,
    const float* __restrict__ wx2, const float* __restrict__ bx2)
{
    __shared__ float s0[DD];
    __shared__ float s1[DD];
    __shared__ float red[128];
    const int b = blockIdx.x;
    const int i = threadIdx.x;
    const float xq = xq_all[b];

    s0[i] = gelu_exact(xq * wq1[i] + bq1[i]);
    __syncthreads();

    {
        float a0 = 0.f, a1 = 0.f, a2 = 0.f, a3 = 0.f;
#pragma unroll 8
        for (int k = 0; k < DD; k += 4) {
            a0 += s0[k + 0] * wq2[(k + 0) * DD + i];
            a1 += s0[k + 1] * wq2[(k + 1) * DD + i];
            a2 += s0[k + 2] * wq2[(k + 2) * DD + i];
            a3 += s0[k + 3] * wq2[(k + 3) * DD + i];
        }
        __syncthreads();
        s1[i] = (a0 + a1) + (a2 + a3) + bq2[i];
    }
    __syncthreads();
    {
        float a0 = 0.f, a1 = 0.f, a2 = 0.f, a3 = 0.f;
#pragma unroll 8
        for (int k = 0; k < DD; k += 4) {
            a0 += s1[k + 0] * wqp[(k + 0) * DD + i];
            a1 += s1[k + 1] * wqp[(k + 1) * DD + i];
            a2 += s1[k + 2] * wqp[(k + 2) * DD + i];
            a3 += s1[k + 3] * wqp[(k + 3) * DD + i];
        }
        __syncthreads();
        s0[i] = (a0 + a1) + (a2 + a3) + bqp[i];   // s0 = q
    }
    __syncthreads();
    {
        float a0 = 0.f, a1 = 0.f, a2 = 0.f, a3 = 0.f;
#pragma unroll 8
        for (int j = 0; j < DD; j += 4) {
            a0 += wkp[i * DD + j + 0] * s0[j + 0];
            a1 += wkp[i * DD + j + 1] * s0[j + 1];
            a2 += wkp[i * DD + j + 2] * s0[j + 2];
            a3 += wkp[i * DD + j + 3] * s0[j + 3];
        }
        __syncthreads();
        s1[i] = (a0 + a1) + (a2 + a3);            // s1 = t
    }
    __syncthreads();
    {
        float a0 = 0.f, a1 = 0.f, a2 = 0.f, a3 = 0.f;
#pragma unroll 8
        for (int j = 0; j < DD; j += 4) {
            a0 += wx2[i * DD + j + 0] * s1[j + 0];
            a1 += wx2[i * DD + j + 1] * s1[j + 1];
            a2 += wx2[i * DD + j + 2] * s1[j + 2];
            a3 += wx2[i * DD + j + 3] * s1[j + 3];
        }
        g_u[b * DD + i] = (a0 + a1) + (a2 + a3);
    }
    red[i] = bx2[i] * s1[i] + bkp[i] * s0[i];
    __syncthreads();
    for (int s = 64; s > 0; s >>= 1) {
        if (i < s) red[i] += red[i + s];
        __syncthreads();
    }
    if (i == 0) g_C[b] = red[0];
}

// ---------------------------------------------------------------------------
// Kernel 2 (dominant): mma.sync bf16 HMMA, error-compensated (3 products).
// Grid (NN/128, BB), 128 threads (4 warps). Tile M=128 items, N=128, K=64.
// score_n = scale*(gelu(x_n@wx1+bx1) . u + C)
// ---------------------------------------------------------------------------
// Shared layout. Row stride 72 bf16 (144 B) -> perfectly conflict-free
// b32 fragment fetches: bank = (4*quad_row + quad_col) mod 32.
static constexpr int STRD  = 72;                    // bf16 elements per row
static constexpr int TILEB = 128 * STRD * 2;        // 18432 bytes
static constexpr int S_AHI = 0;
static constexpr int S_ALO = S_AHI + TILEB;
static constexpr int S_BHI = S_ALO + TILEB;
static constexpr int S_BLO = S_BHI + TILEB;
static constexpr int S_US  = S_BLO + TILEB;
static constexpr int S_BXS = S_US + 512;
static constexpr int S_TOT = S_BXS + 512;

__device__ __forceinline__ unsigned long long pack4bf16(float a, float b,
                                                        float c, float d) {
    return (unsigned long long)__bfloat16_as_ushort(__float2bfloat16(a))
         | ((unsigned long long)__bfloat16_as_ushort(__float2bfloat16(b)) << 16)
         | ((unsigned long long)__bfloat16_as_ushort(__float2bfloat16(c)) << 32)
         | ((unsigned long long)__bfloat16_as_ushort(__float2bfloat16(d)) << 48);
}

__global__ void __launch_bounds__(128) k2_scores_hmma(
    const float* __restrict__ x_items,
    const float* __restrict__ bx1)
{
    extern __shared__ char smem[];
    const int tid = threadIdx.x;
    const int wid = tid >> 5;
    const int lid = tid & 31;
    const int qr  = lid >> 2;   // quad row (0..7)
    const int qc  = lid & 3;    // quad col (0..3)
    const int b   = blockIdx.y;
    const int tile0 = blockIdx.x * 128;

    float* us  = reinterpret_cast<float*>(smem + S_US);
    float* bxs = reinterpret_cast<float*>(smem + S_BXS);
    us[tid]  = g_u[b * DD + tid];
    bxs[tid] = bx1[tid];
    const float Cs = g_C[b];

    // ---- B tiles: pre-split weights [n*64+k] -> shared [n][k] stride 72
    {
        const unsigned long long* wh = reinterpret_cast<const unsigned long long*>(g_wt_hi);
        const unsigned long long* wl = reinterpret_cast<const unsigned long long*>(g_wt_lo);
        for (int c = tid; c < 2048; c += 128) {        // 2048 chunks of 4 bf16
            int n  = c >> 4;
            int k4 = (c & 15) << 2;
            uint32_t off = (uint32_t)(n * STRD + k4) * 2u;
            *reinterpret_cast<unsigned long long*>(smem + S_BHI + off) = wh[c];
            *reinterpret_cast<unsigned long long*>(smem + S_BLO + off) = wl[c];
        }
    }

    // ---- A tile: 128 items x 64 f32 -> bf16 hi/lo, shared [item][k] stride 72
    {
        const float4* xt = reinterpret_cast<const float4*>(
            x_items + ((size_t)b * NN + (size_t)tile0) * IDM);
        for (int c = tid; c < 2048; c += 128) {        // float4 chunks
            float4 v = xt[c];
            int item = c >> 4;
            int k4   = (c & 15) << 2;
            float hx = __bfloat162float(__float2bfloat16(v.x));
            float hy = __bfloat162float(__float2bfloat16(v.y));
            float hz = __bfloat162float(__float2bfloat16(v.z));
            float hw = __bfloat162float(__float2bfloat16(v.w));
            uint32_t off = (uint32_t)(item * STRD + k4) * 2u;
            *reinterpret_cast<unsigned long long*>(smem + S_AHI + off) =
                pack4bf16(v.x, v.y, v.z, v.w);
            *reinterpret_cast<unsigned long long*>(smem + S_ALO + off) =
                pack4bf16(v.x - hx, v.y - hy, v.z - hz, v.w - hw);
        }
    }
    __syncthreads();

    // ---- A fragments into registers: [mtile][kstep][4]
    uint32_t AH[2][4][4], AL[2][4][4];
#pragma unroll
    for (int mt = 0; mt < 2; mt++) {
#pragma unroll
        for (int ks = 0; ks < 4; ks++) {
            int r0 = wid * 32 + mt * 16 + qr;
            int k0 = ks * 16 + qc * 2;
            uint32_t o00 = (uint32_t)(r0 * STRD + k0) * 2u;
            uint32_t o10 = (uint32_t)((r0 + 8) * STRD + k0) * 2u;
            AH[mt][ks][0] = *reinterpret_cast<const uint32_t*>(smem + S_AHI + o00);
            AH[mt][ks][1] = *reinterpret_cast<const uint32_t*>(smem + S_AHI + o10);
            AH[mt][ks][2] = *reinterpret_cast<const uint32_t*>(smem + S_AHI + o00 + 16);
            AH[mt][ks][3] = *reinterpret_cast<const uint32_t*>(smem + S_AHI + o10 + 16);
            AL[mt][ks][0] = *reinterpret_cast<const uint32_t*>(smem + S_ALO + o00);
            AL[mt][ks][1] = *reinterpret_cast<const uint32_t*>(smem + S_ALO + o10);
            AL[mt][ks][2] = *reinterpret_cast<const uint32_t*>(smem + S_ALO + o00 + 16);
            AL[mt][ks][3] = *reinterpret_cast<const uint32_t*>(smem + S_ALO + o10 + 16);
        }
    }

    // ---- Mainloop over 16 n-tiles of 8 columns
    float sc[2][2] = {{0.f, 0.f}, {0.f, 0.f}};   // [mtile][row-half]
#pragma unroll 1
    for (int nt = 0; nt < 16; nt++) {
        float c0[4] = {0.f, 0.f, 0.f, 0.f};
        float c1[4] = {0.f, 0.f, 0.f, 0.f};
#pragma unroll
        for (int ks = 0; ks < 4; ks++) {
            uint32_t bo = (uint32_t)((nt * 8 + qr) * STRD + ks * 16 + qc * 2) * 2u;
            uint32_t bh0 = *reinterpret_cast<const uint32_t*>(smem + S_BHI + bo);
            uint32_t bh1 = *reinterpret_cast<const uint32_t*>(smem + S_BHI + bo + 16);
            uint32_t bl0 = *reinterpret_cast<const uint32_t*>(smem + S_BLO + bo);
            uint32_t bl1 = *reinterpret_cast<const uint32_t*>(smem + S_BLO + bo + 16);
            mma16816(c0, AH[0][ks], bh0, bh1);
            mma16816(c0, AH[0][ks], bl0, bl1);
            mma16816(c0, AL[0][ks], bh0, bh1);
            mma16816(c1, AH[1][ks], bh0, bh1);
            mma16816(c1, AH[1][ks], bl0, bl1);
            mma16816(c1, AL[1][ks], bh0, bh1);
        }
        // epilogue for this n-tile: cols n0, n0+1 for this lane
        int n0 = nt * 8 + qc * 2;
        float2 bias = *reinterpret_cast<const float2*>(&bxs[n0]);
        float2 uu   = *reinterpret_cast<const float2*>(&us[n0]);
        sc[0][0] += gelu_exact(c0[0] + bias.x) * uu.x + gelu_exact(c0[1] + bias.y) * uu.y;
        sc[0][1] += gelu_exact(c0[2] + bias.x) * uu.x + gelu_exact(c0[3] + bias.y) * uu.y;
        sc[1][0] += gelu_exact(c1[0] + bias.x) * uu.x + gelu_exact(c1[1] + bias.y) * uu.y;
        sc[1][1] += gelu_exact(c1[2] + bias.x) * uu.x + gelu_exact(c1[3] + bias.y) * uu.y;
    }

    // ---- quad reduction (lanes sharing qr) and store
#pragma unroll
    for (int mt = 0; mt < 2; mt++) {
#pragma unroll
        for (int h = 0; h < 2; h++) {
            float v = sc[mt][h];
            v += __shfl_xor_sync(0xffffffffu, v, 1);
            v += __shfl_xor_sync(0xffffffffu, v, 2);
            sc[mt][h] = v;
        }
    }
    if (qc == 0) {
#pragma unroll
        for (int mt = 0; mt < 2; mt++) {
#pragma unroll
            for (int h = 0; h < 2; h++) {
                int item = tile0 + wid * 32 + mt * 16 + h * 8 + qr;
                g_scores[b * NN + item] =
                    0.08838834764831845f * (sc[mt][h] + Cs);
            }
        }
    }
}

// ---------------------------------------------------------------------------
// Kernel 3: sparsemax (bisection + exact refine) + sparse readout + head MLP.
// ---------------------------------------------------------------------------
__global__ void __launch_bounds__(512) k3_sparsemax_out(
    const float* __restrict__ x_items,
    const float* __restrict__ wx1, const float* __restrict__ bx1,
    const float* __restrict__ wx2, const float* __restrict__ bx2,
    const float* __restrict__ wvp, const float* __restrict__ bvp,
    const float* __restrict__ wp1, const float* __restrict__ bp1,
    const float* __restrict__ wp2, const float* __restrict__ bp2,
    float* __restrict__ out)
{
    __shared__ float rpart[16];
    __shared__ float rpart2[16];
    __shared__ float accg[DD];
    __shared__ float buf1[DD];
    __shared__ float buf2[DD];

    const int tid  = threadIdx.x;
    const int b    = blockIdx.x;
    const int lane = tid & 31;
    const int wid  = tid >> 5;
    const float* sc = g_scores + b * NN;

    float z[32];
#pragma unroll
    for (int j = 0; j < 32; j++) z[j] = sc[tid + j * 512];

    float m = z[0];
#pragma unroll
    for (int j = 1; j < 32; j++) m = fmaxf(m, z[j]);
#pragma unroll
    for (int o = 16; o > 0; o >>= 1) m = fmaxf(m, __shfl_xor_sync(0xffffffffu, m, o));
    if (lane == 0) rpart[wid] = m;
    __syncthreads();
    float zmax = rpart[0];
#pragma unroll
    for (int j = 1; j < 16; j++) zmax = fmaxf(zmax, rpart[j]);

    float lo = zmax - 1.0f, hi = zmax;
    for (int it = 0; it < 34; it++) {
        float mid = 0.5f * (lo + hi);
        float s = 0.f;
#pragma unroll
        for (int j = 0; j < 32; j++) s += fmaxf(z[j] - mid, 0.f);
#pragma unroll
        for (int o = 16; o > 0; o >>= 1) s += __shfl_xor_sync(0xffffffffu, s, o);
        __syncthreads();
        if (lane == 0) rpart[wid] = s;
        __syncthreads();
        float f = 0.f;
#pragma unroll
        for (int j = 0; j < 16; j++) f += rpart[j];
        if (f > 1.0f) lo = mid; else hi = mid;
    }
    const float tau0 = 0.5f * (lo + hi);

    float ssum = 0.f, scnt = 0.f;
#pragma unroll
    for (int j = 0; j < 32; j++) {
        if (z[j] > tau0) { ssum += z[j]; scnt += 1.f; }
    }
#pragma unroll
    for (int o = 16; o > 0; o >>= 1) {
        ssum += __shfl_xor_sync(0xffffffffu, ssum, o);
        scnt += __shfl_xor_sync(0xffffffffu, scnt, o);
    }
    __syncthreads();
    if (lane == 0) { rpart[wid] = ssum; rpart2[wid] = scnt; }
    __syncthreads();
    float S = 0.f, K = 0.f;
#pragma unroll
    for (int j = 0; j < 16; j++) { S += rpart[j]; K += rpart2[j]; }
    const float tau = (S - 1.0f) / K;

    if (tid < DD) accg[tid] = 0.f;
    __syncthreads();

    for (int base = wid * 32; base < NN; base += 512) {
        float zz = sc[base + lane];
        unsigned msk = __ballot_sync(0xffffffffu, zz > tau0);
        while (msk) {
            int j = __ffs(msk) - 1;
            msk &= msk - 1;
            float w = fmaxf(__shfl_sync(0xffffffffu, zz, j) - tau, 0.f);
            const float* xr = x_items + ((size_t)b * NN + (size_t)(base + j)) * IDM;
            float x0 = xr[2 * lane], x1 = xr[2 * lane + 1];
            float a0 = bx1[lane];
            float a1 = bx1[lane + 32];
            float a2 = bx1[lane + 64];
            float a3 = bx1[lane + 96];
#pragma unroll
            for (int k = 0; k < IDM; k++) {
                float xv = __shfl_sync(0xffffffffu, (k & 1) ? x1 : x0, k >> 1);
                a0 += xv * wx1[k * DD + lane];
                a1 += xv * wx1[k * DD + lane + 32];
                a2 += xv * wx1[k * DD + lane + 64];
                a3 += xv * wx1[k * DD + lane + 96];
            }
            atomicAdd(&accg[lane],      w * gelu_exact(a0));
            atomicAdd(&accg[lane + 32], w * gelu_exact(a1));
            atomicAdd(&accg[lane + 64], w * gelu_exact(a2));
            atomicAdd(&accg[lane + 96], w * gelu_exact(a3));
        }
    }
    __syncthreads();

    if (tid < DD) {
        float hv = bx2[tid];
        for (int k = 0; k < DD; k++) hv += accg[k] * wx2[k * DD + tid];
        buf1[tid] = hv;
    }
    __syncthreads();
    if (tid < DD) {
        float zv = bvp[tid];
        for (int k = 0; k < DD; k++) zv += buf1[k] * wvp[k * DD + tid];
        buf2[tid] = zv;
    }
    __syncthreads();
    if (tid < DD) {
        float pv = bp1[tid];
        for (int k = 0; k < DD; k++) pv += buf2[k] * wp1[k * DD + tid];
        buf1[tid] = gelu_exact(pv);
    }
    __syncthreads();
    if (tid < NCLS) {
        float o = bp2[tid];
        for (int k = 0; k < DD; k++) o += buf1[k] * wp2[k * NCLS + tid];
        out[b * NCLS + tid] = o;
    }
}

// ---------------------------------------------------------------------------
extern "C" void kernel_launch(void* const* d_in, const int* in_sizes, int n_in,
                              void* d_out, int out_size)
{
    const float* x_items = (const float*)d_in[0];
    const float* x_query = (const float*)d_in[1];
    const float* wx1 = (const float*)d_in[2];
    const float* bx1 = (const float*)d_in[3];
    const float* wx2 = (const float*)d_in[4];
    const float* bx2 = (const float*)d_in[5];
    const float* wq1 = (const float*)d_in[6];
    const float* bq1 = (const float*)d_in[7];
    const float* wq2 = (const float*)d_in[8];
    const float* bq2 = (const float*)d_in[9];
    const float* wqp = (const float*)d_in[10];
    const float* bqp = (const float*)d_in[11];
    const float* wkp = (const float*)d_in[12];
    const float* bkp = (const float*)d_in[13];
    const float* wvp = (const float*)d_in[14];
    const float* bvp = (const float*)d_in[15];
    const float* wp1 = (const float*)d_in[16];
    const float* bp1 = (const float*)d_in[17];
    const float* wp2 = (const float*)d_in[18];
    const float* bp2 = (const float*)d_in[19];
    float* out = (float*)d_out;

    cudaFuncSetAttribute(k2_scores_hmma,
                         cudaFuncAttributeMaxDynamicSharedMemorySize, S_TOT);

    k0_prep_weights<<<(IDM * DD + 255) / 256, 256>>>(wx1);

    k1_precompute<<<BB, 128>>>(x_query, wq1, bq1, wq2, bq2, wqp, bqp,
                               wkp, bkp, wx2, bx2);

    dim3 g2(NN / 128, BB);
    k2_scores_hmma<<<g2, 128, S_TOT>>>(x_items, bx1);

    k3_sparsemax_out<<<BB, 512>>>(x_items, wx1, bx1, wx2, bx2,
                                  wvp, bvp, wp1, bp1, wp2, bp2, out);
}

// round 7
// speedup vs baseline: 1.4567x; 1.1809x over previous
#include <cuda_runtime.h>
#include <cuda_bf16.h>
#include <cstdint>

#define BB   32
#define NN   16384
#define DD   128
#define IDM  64
#define NCLS 10

// ---------------------------------------------------------------------------
// Scratch (device globals — no allocation allowed)
// ---------------------------------------------------------------------------
__device__ float g_scores[BB * NN];
__device__ float g_u[BB * DD];
__device__ float g_C[BB];
__device__ __align__(16) __nv_bfloat16 g_wt_hi[DD * IDM];  // [n*64 + k]
__device__ __align__(16) __nv_bfloat16 g_wt_lo[DD * IDM];

__device__ __forceinline__ float gelu_exact(float x) {
    return 0.5f * x * (1.0f + erff(x * 0.7071067811865475f));
}

// m16n8k16 row.col bf16 MMA with f32 accumulate (arch-stable, sm_80+)
__device__ __forceinline__ void mma16816(float* c, const uint32_t* a,
                                         uint32_t b0, uint32_t b1) {
    asm volatile(
        "mma.sync.aligned.m16n8k16.row.col.f32.bf16.bf16.f32 "
        "{%0,%1,%2,%3}, {%4,%5,%6,%7}, {%8,%9}, {%0,%1,%2,%3};"
        : "+f"(c[0]), "+f"(c[1]), "+f"(c[2]), "+f"(c[3])
        : "r"(a[0]), "r"(a[1]), "r"(a[2]), "r"(a[3]), "r"(b0), "r"(b1));
}

// split float2 -> packed bf16x2 hi and lo (error compensation)
__device__ __forceinline__ void split2(float2 v, uint32_t& hi, uint32_t& lo) {
    __nv_bfloat16 hx = __float2bfloat16(v.x);
    __nv_bfloat16 hy = __float2bfloat16(v.y);
    hi = (uint32_t)__bfloat16_as_ushort(hx)
       | ((uint32_t)__bfloat16_as_ushort(hy) << 16);
    __nv_bfloat16 lx = __float2bfloat16(v.x - __bfloat162float(hx));
    __nv_bfloat16 ly = __float2bfloat16(v.y - __bfloat162float(hy));
    lo = (uint32_t)__bfloat16_as_ushort(lx)
       | ((uint32_t)__bfloat16_as_ushort(ly) << 16);
}

// ---------------------------------------------------------------------------
// Kernel 1: per-batch precompute (query MLP chain, u, C) + weight prep.
// 32 blocks x 128 threads. Block b also splits its 256-element slice of wx1.
// ---------------------------------------------------------------------------
__global__ void __launch_bounds__(128) k1_precompute(
    const float* __restrict__ xq_all,
    const float* __restrict__ wx1,
    const float* __restrict__ wq1, const float* __restrict__ bq1,
    const float* __restrict__ wq2, const float* __restrict__ bq2,
    const float* __restrict__ wqp, const float* __restrict__ bqp,
    const float* __restrict__ wkp, const float* __restrict__ bkp,
    const float* __restrict__ wx2, const float* __restrict__ bx2)
{
    __shared__ float s0[DD];
    __shared__ float s1[DD];
    __shared__ float red[128];
    const int b = blockIdx.x;
    const int i = threadIdx.x;
    const float xq = xq_all[b];

    // ---- weight prep slice: transpose wx1 [k*128+n] -> [n*64+k], split hi/lo
    {
        int base = b * 256;
#pragma unroll
        for (int t = 0; t < 2; t++) {
            int idx = base + i + t * 128;     // idx = k*128 + n
            int k = idx >> 7;
            int n = idx & 127;
            float w = wx1[idx];
            __nv_bfloat16 hi = __float2bfloat16(w);
            __nv_bfloat16 lo = __float2bfloat16(w - __bfloat162float(hi));
            g_wt_hi[n * IDM + k] = hi;
            g_wt_lo[n * IDM + k] = lo;
        }
    }

    s0[i] = gelu_exact(xq * wq1[i] + bq1[i]);
    __syncthreads();

    {
        float a0 = 0.f, a1 = 0.f, a2 = 0.f, a3 = 0.f;
#pragma unroll 8
        for (int k = 0; k < DD; k += 4) {
            a0 += s0[k + 0] * wq2[(k + 0) * DD + i];
            a1 += s0[k + 1] * wq2[(k + 1) * DD + i];
            a2 += s0[k + 2] * wq2[(k + 2) * DD + i];
            a3 += s0[k + 3] * wq2[(k + 3) * DD + i];
        }
        __syncthreads();
        s1[i] = (a0 + a1) + (a2 + a3) + bq2[i];
    }
    __syncthreads();
    {
        float a0 = 0.f, a1 = 0.f, a2 = 0.f, a3 = 0.f;
#pragma unroll 8
        for (int k = 0; k < DD; k += 4) {
            a0 += s1[k + 0] * wqp[(k + 0) * DD + i];
            a1 += s1[k + 1] * wqp[(k + 1) * DD + i];
            a2 += s1[k + 2] * wqp[(k + 2) * DD + i];
            a3 += s1[k + 3] * wqp[(k + 3) * DD + i];
        }
        __syncthreads();
        s0[i] = (a0 + a1) + (a2 + a3) + bqp[i];   // s0 = q
    }
    __syncthreads();
    {
        float a0 = 0.f, a1 = 0.f, a2 = 0.f, a3 = 0.f;
#pragma unroll 8
        for (int j = 0; j < DD; j += 4) {
            a0 += wkp[i * DD + j + 0] * s0[j + 0];
            a1 += wkp[i * DD + j + 1] * s0[j + 1];
            a2 += wkp[i * DD + j + 2] * s0[j + 2];
            a3 += wkp[i * DD + j + 3] * s0[j + 3];
        }
        __syncthreads();
        s1[i] = (a0 + a1) + (a2 + a3);            // s1 = t
    }
    __syncthreads();
    {
        float a0 = 0.f, a1 = 0.f, a2 = 0.f, a3 = 0.f;
#pragma unroll 8
        for (int j = 0; j < DD; j += 4) {
            a0 += wx2[i * DD + j + 0] * s1[j + 0];
            a1 += wx2[i * DD + j + 1] * s1[j + 1];
            a2 += wx2[i * DD + j + 2] * s1[j + 2];
            a3 += wx2[i * DD + j + 3] * s1[j + 3];
        }
        g_u[b * DD + i] = (a0 + a1) + (a2 + a3);
    }
    red[i] = bx2[i] * s1[i] + bkp[i] * s0[i];
    __syncthreads();
    for (int s = 64; s > 0; s >>= 1) {
        if (i < s) red[i] += red[i + s];
        __syncthreads();
    }
    if (i == 0) g_C[b] = red[0];
}

// ---------------------------------------------------------------------------
// Kernel 2 (dominant): mma.sync bf16 HMMA, error-compensated (3 products).
// Grid (NN/128, BB), 128 threads (4 warps). Tile M=128 items, N=128, K=64.
// A fragments loaded DIRECTLY from global (float2 -> bf16 hi/lo in regs).
// B (pre-split weights) staged in shared. score = scale*(gelu(xW+b).u + C).
// ---------------------------------------------------------------------------
static constexpr int STRD  = 72;                    // bf16 elements per row
static constexpr int TILEB = 128 * STRD * 2;        // 18432 bytes
static constexpr int S_BHI = 0;
static constexpr int S_BLO = S_BHI + TILEB;
static constexpr int S_US  = S_BLO + TILEB;
static constexpr int S_BXS = S_US + 512;
static constexpr int S_TOT = S_BXS + 512;

__global__ void __launch_bounds__(128) k2_scores_hmma(
    const float* __restrict__ x_items,
    const float* __restrict__ bx1)
{
    extern __shared__ char smem[];
    const int tid = threadIdx.x;
    const int wid = tid >> 5;
    const int lid = tid & 31;
    const int qr  = lid >> 2;   // quad row (0..7)
    const int qc  = lid & 3;    // quad col (0..3)
    const int b   = blockIdx.y;
    const int tile0 = blockIdx.x * 128;

    float* us  = reinterpret_cast<float*>(smem + S_US);
    float* bxs = reinterpret_cast<float*>(smem + S_BXS);
    us[tid]  = g_u[b * DD + tid];
    bxs[tid] = bx1[tid];
    const float Cs = g_C[b];

    // ---- B tiles: pre-split weights [n*64+k] -> shared [n][k] stride 72
    {
        const unsigned long long* wh = reinterpret_cast<const unsigned long long*>(g_wt_hi);
        const unsigned long long* wl = reinterpret_cast<const unsigned long long*>(g_wt_lo);
        for (int c = tid; c < 2048; c += 128) {        // 2048 chunks of 4 bf16
            int n  = c >> 4;
            int k4 = (c & 15) << 2;
            uint32_t off = (uint32_t)(n * STRD + k4) * 2u;
            *reinterpret_cast<unsigned long long*>(smem + S_BHI + off) = wh[c];
            *reinterpret_cast<unsigned long long*>(smem + S_BLO + off) = wl[c];
        }
    }

    // ---- A fragments: direct from global, hi/lo split in registers
    uint32_t AH[2][4][4], AL[2][4][4];
    {
        const float* xb = x_items + ((size_t)b * NN + (size_t)tile0) * IDM;
#pragma unroll
        for (int mt = 0; mt < 2; mt++) {
            int r0 = wid * 32 + mt * 16 + qr;
#pragma unroll
            for (int ks = 0; ks < 4; ks++) {
                int k0 = ks * 16 + qc * 2;
                float2 v00 = *reinterpret_cast<const float2*>(xb + (size_t)r0 * IDM + k0);
                float2 v10 = *reinterpret_cast<const float2*>(xb + (size_t)(r0 + 8) * IDM + k0);
                float2 v01 = *reinterpret_cast<const float2*>(xb + (size_t)r0 * IDM + k0 + 8);
                float2 v11 = *reinterpret_cast<const float2*>(xb + (size_t)(r0 + 8) * IDM + k0 + 8);
                split2(v00, AH[mt][ks][0], AL[mt][ks][0]);
                split2(v10, AH[mt][ks][1], AL[mt][ks][1]);
                split2(v01, AH[mt][ks][2], AL[mt][ks][2]);
                split2(v11, AH[mt][ks][3], AL[mt][ks][3]);
            }
        }
    }
    __syncthreads();

    // ---- Mainloop over 16 n-tiles of 8 columns
    float sc[2][2] = {{0.f, 0.f}, {0.f, 0.f}};   // [mtile][row-half]
#pragma unroll 1
    for (int nt = 0; nt < 16; nt++) {
        float c0[4] = {0.f, 0.f, 0.f, 0.f};
        float c1[4] = {0.f, 0.f, 0.f, 0.f};
#pragma unroll
        for (int ks = 0; ks < 4; ks++) {
            uint32_t bo = (uint32_t)((nt * 8 + qr) * STRD + ks * 16 + qc * 2) * 2u;
            uint32_t bh0 = *reinterpret_cast<const uint32_t*>(smem + S_BHI + bo);
            uint32_t bh1 = *reinterpret_cast<const uint32_t*>(smem + S_BHI + bo + 16);
            uint32_t bl0 = *reinterpret_cast<const uint32_t*>(smem + S_BLO + bo);
            uint32_t bl1 = *reinterpret_cast<const uint32_t*>(smem + S_BLO + bo + 16);
            mma16816(c0, AH[0][ks], bh0, bh1);
            mma16816(c0, AH[0][ks], bl0, bl1);
            mma16816(c0, AL[0][ks], bh0, bh1);
            mma16816(c1, AH[1][ks], bh0, bh1);
            mma16816(c1, AH[1][ks], bl0, bl1);
            mma16816(c1, AL[1][ks], bh0, bh1);
        }
        int n0 = nt * 8 + qc * 2;
        float2 bias = *reinterpret_cast<const float2*>(&bxs[n0]);
        float2 uu   = *reinterpret_cast<const float2*>(&us[n0]);
        sc[0][0] += gelu_exact(c0[0] + bias.x) * uu.x + gelu_exact(c0[1] + bias.y) * uu.y;
        sc[0][1] += gelu_exact(c0[2] + bias.x) * uu.x + gelu_exact(c0[3] + bias.y) * uu.y;
        sc[1][0] += gelu_exact(c1[0] + bias.x) * uu.x + gelu_exact(c1[1] + bias.y) * uu.y;
        sc[1][1] += gelu_exact(c1[2] + bias.x) * uu.x + gelu_exact(c1[3] + bias.y) * uu.y;
    }

    // ---- quad reduction (lanes sharing qr) and store
#pragma unroll
    for (int mt = 0; mt < 2; mt++) {
#pragma unroll
        for (int h = 0; h < 2; h++) {
            float v = sc[mt][h];
            v += __shfl_xor_sync(0xffffffffu, v, 1);
            v += __shfl_xor_sync(0xffffffffu, v, 2);
            sc[mt][h] = v;
        }
    }
    if (qc == 0) {
#pragma unroll
        for (int mt = 0; mt < 2; mt++) {
#pragma unroll
            for (int h = 0; h < 2; h++) {
                int item = tile0 + wid * 32 + mt * 16 + h * 8 + qr;
                g_scores[b * NN + item] =
                    0.08838834764831845f * (sc[mt][h] + Cs);
            }
        }
    }
}

// ---------------------------------------------------------------------------
// Kernel 3: sparsemax (Michelot + bisection + exact refine) + sparse readout
// + head MLP. 32 blocks x 1024 threads (32 warps), z = 16 regs/thread.
// ---------------------------------------------------------------------------
__global__ void __launch_bounds__(1024) k3_sparsemax_out(
    const float* __restrict__ x_items,
    const float* __restrict__ wx1, const float* __restrict__ bx1,
    const float* __restrict__ wx2, const float* __restrict__ bx2,
    const float* __restrict__ wvp, const float* __restrict__ bvp,
    const float* __restrict__ wp1, const float* __restrict__ bp1,
    const float* __restrict__ wp2, const float* __restrict__ bp2,
    float* __restrict__ out)
{
    __shared__ float sP[32];
    __shared__ float sP2[32];
    __shared__ float bc[2];
    __shared__ float accg[DD];
    __shared__ float buf1[DD];
    __shared__ float buf2[DD];

    const int tid  = threadIdx.x;
    const int b    = blockIdx.x;
    const int lane = tid & 31;
    const int wid  = tid >> 5;
    const float* sc = g_scores + b * NN;

    if (tid < DD) accg[tid] = 0.f;

    float z[16];
#pragma unroll
    for (int j = 0; j < 16; j++) z[j] = sc[tid + j * 1024];

    // ---- block max ----
    float m = z[0];
#pragma unroll
    for (int j = 1; j < 16; j++) m = fmaxf(m, z[j]);
#pragma unroll
    for (int o = 16; o > 0; o >>= 1) m = fmaxf(m, __shfl_xor_sync(0xffffffffu, m, o));
    if (lane == 0) sP[wid] = m;
    __syncthreads();
    if (wid == 0) {
        float v = sP[lane];
#pragma unroll
        for (int o = 16; o > 0; o >>= 1) v = fmaxf(v, __shfl_xor_sync(0xffffffffu, v, o));
        if (lane == 0) bc[0] = v;
    }
    __syncthreads();
    const float zmax = bc[0];

    // ---- Michelot fixed-point: tau <- (sum_{z>tau} z - 1) / count, 8 rounds
    float tau = zmax - 1.0f;
#pragma unroll 1
    for (int it = 0; it < 8; it++) {
        float s = 0.f, c = 0.f;
#pragma unroll
        for (int j = 0; j < 16; j++) {
            if (z[j] > tau) { s += z[j]; c += 1.f; }
        }
#pragma unroll
        for (int o = 16; o > 0; o >>= 1) {
            s += __shfl_xor_sync(0xffffffffu, s, o);
            c += __shfl_xor_sync(0xffffffffu, c, o);
        }
        if (lane == 0) { sP[wid] = s; sP2[wid] = c; }
        __syncthreads();
        if (wid == 0) {
            float s2 = sP[lane], c2 = sP2[lane];
#pragma unroll
            for (int o = 16; o > 0; o >>= 1) {
                s2 += __shfl_xor_sync(0xffffffffu, s2, o);
                c2 += __shfl_xor_sync(0xffffffffu, c2, o);
            }
            if (lane == 0) bc[0] = (s2 - 1.0f) / c2;
        }
        __syncthreads();
        tau = bc[0];
    }

    // ---- bisection polish in [tau, zmax], 18 rounds
    float lo = tau, hi = zmax;
#pragma unroll 1
    for (int it = 0; it < 18; it++) {
        float mid = 0.5f * (lo + hi);
        float s = 0.f;
#pragma unroll
        for (int j = 0; j < 16; j++) s += fmaxf(z[j] - mid, 0.f);
#pragma unroll
        for (int o = 16; o > 0; o >>= 1) s += __shfl_xor_sync(0xffffffffu, s, o);
        if (lane == 0) sP[wid] = s;
        __syncthreads();
        if (wid == 0) {
            float s2 = sP[lane];
#pragma unroll
            for (int o = 16; o > 0; o >>= 1) s2 += __shfl_xor_sync(0xffffffffu, s2, o);
            if (lane == 0) bc[0] = s2;
        }
        __syncthreads();
        if (bc[0] > 1.0f) lo = mid; else hi = mid;
        __syncthreads();
    }
    const float tau0 = 0.5f * (lo + hi);

    // ---- exact refine: support {z > tau0}, tau = (S-1)/k
    {
        float s = 0.f, c = 0.f;
#pragma unroll
        for (int j = 0; j < 16; j++) {
            if (z[j] > tau0) { s += z[j]; c += 1.f; }
        }
#pragma unroll
        for (int o = 16; o > 0; o >>= 1) {
            s += __shfl_xor_sync(0xffffffffu, s, o);
            c += __shfl_xor_sync(0xffffffffu, c, o);
        }
        if (lane == 0) { sP[wid] = s; sP2[wid] = c; }
        __syncthreads();
        if (wid == 0) {
            float s2 = sP[lane], c2 = sP2[lane];
#pragma unroll
            for (int o = 16; o > 0; o >>= 1) {
                s2 += __shfl_xor_sync(0xffffffffu, s2, o);
                c2 += __shfl_xor_sync(0xffffffffu, c2, o);
            }
            if (lane == 0) bc[1] = (s2 - 1.0f) / c2;
        }
        __syncthreads();
    }
    const float tauF = bc[1];

    // ---- sparse accumulation: Gbar = sum_n attn_n * gelu(x_n@wx1+bx1)
    // Each warp ballots its own registers; window base = wid*32 + j*1024.
#pragma unroll 1
    for (int j = 0; j < 16; j++) {
        float zz = z[j];
        unsigned msk = __ballot_sync(0xffffffffu, zz > tau0);
        while (msk) {
            int jb = __ffs(msk) - 1;
            msk &= msk - 1;
            float w = fmaxf(__shfl_sync(0xffffffffu, zz, jb) - tauF, 0.f);
            int item = wid * 32 + j * 1024 + jb;
            const float* xr = x_items + ((size_t)b * NN + (size_t)item) * IDM;
            float x0 = xr[2 * lane], x1 = xr[2 * lane + 1];
            float a0 = bx1[lane];
            float a1 = bx1[lane + 32];
            float a2 = bx1[lane + 64];
            float a3 = bx1[lane + 96];
#pragma unroll
            for (int k = 0; k < IDM; k++) {
                float xv = __shfl_sync(0xffffffffu, (k & 1) ? x1 : x0, k >> 1);
                a0 += xv * wx1[k * DD + lane];
                a1 += xv * wx1[k * DD + lane + 32];
                a2 += xv * wx1[k * DD + lane + 64];
                a3 += xv * wx1[k * DD + lane + 96];
            }
            atomicAdd(&accg[lane],      w * gelu_exact(a0));
            atomicAdd(&accg[lane + 32], w * gelu_exact(a1));
            atomicAdd(&accg[lane + 64], w * gelu_exact(a2));
            atomicAdd(&accg[lane + 96], w * gelu_exact(a3));
        }
    }
    __syncthreads();

    // ---- head MLP (first 128 threads)
    if (tid < DD) {
        float hv = bx2[tid];
#pragma unroll 8
        for (int k = 0; k < DD; k++) hv += accg[k] * wx2[k * DD + tid];
        buf1[tid] = hv;
    }
    __syncthreads();
    if (tid < DD) {
        float zv = bvp[tid];
#pragma unroll 8
        for (int k = 0; k < DD; k++) zv += buf1[k] * wvp[k * DD + tid];
        buf2[tid] = zv;
    }
    __syncthreads();
    if (tid < DD) {
        float pv = bp1[tid];
#pragma unroll 8
        for (int k = 0; k < DD; k++) pv += buf2[k] * wp1[k * DD + tid];
        buf1[tid] = gelu_exact(pv);
    }
    __syncthreads();
    if (tid < NCLS) {
        float o = bp2[tid];
#pragma unroll 8
        for (int k = 0; k < DD; k++) o += buf1[k] * wp2[k * NCLS + tid];
        out[b * NCLS + tid] = o;
    }
}

// ---------------------------------------------------------------------------
extern "C" void kernel_launch(void* const* d_in, const int* in_sizes, int n_in,
                              void* d_out, int out_size)
{
    const float* x_items = (const float*)d_in[0];
    const float* x_query = (const float*)d_in[1];
    const float* wx1 = (const float*)d_in[2];
    const float* bx1 = (const float*)d_in[3];
    const float* wx2 = (const float*)d_in[4];
    const float* bx2 = (const float*)d_in[5];
    const float* wq1 = (const float*)d_in[6];
    const float* bq1 = (const float*)d_in[7];
    const float* wq2 = (const float*)d_in[8];
    const float* bq2 = (const float*)d_in[9];
    const float* wqp = (const float*)d_in[10];
    const float* bqp = (const float*)d_in[11];
    const float* wkp = (const float*)d_in[12];
    const float* bkp = (const float*)d_in[13];
    const float* wvp = (const float*)d_in[14];
    const float* bvp = (const float*)d_in[15];
    const float* wp1 = (const float*)d_in[16];
    const float* bp1 = (const float*)d_in[17];
    const float* wp2 = (const float*)d_in[18];
    const float* bp2 = (const float*)d_in[19];
    float* out = (float*)d_out;

    cudaFuncSetAttribute(k2_scores_hmma,
                         cudaFuncAttributeMaxDynamicSharedMemorySize, S_TOT);

    k1_precompute<<<BB, 128>>>(x_query, wx1, wq1, bq1, wq2, bq2, wqp, bqp,
                               wkp, bkp, wx2, bx2);

    dim3 g2(NN / 128, BB);
    k2_scores_hmma<<<g2, 128, S_TOT>>>(x_items, bx1);

    k3_sparsemax_out<<<BB, 1024>>>(x_items, wx1, bx1, wx2, bx2,
                                   wvp, bvp, wp1, bp1, wp2, bp2, out);
}

// round 8
// speedup vs baseline: 1.5986x; 1.0974x over previous
#include <cuda_runtime.h>
#include <cuda_fp16.h>
#include <cstdint>

#define BB   32
#define NN   16384
#define DD   128
#define IDM  64
#define NCLS 10

// ---------------------------------------------------------------------------
// Scratch (device globals — no allocation allowed)
// ---------------------------------------------------------------------------
__device__ float g_scores[BB * NN];
__device__ float g_u[BB * DD];
__device__ float g_C[BB];
// fp16 weight fragments for k2, slot s=(nt*4+ks)*32+lid, 8B each:
// { w(n,k0),w(n,k0+1) | w(n,k0+8),w(n,k0+9) }, n=nt*8+(lid>>2), k0=ks*16+(lid&3)*2
__device__ __align__(16) unsigned long long g_wfrag[2048];

__device__ __forceinline__ float gelu_exact(float x) {
    return 0.5f * x * (1.0f + erff(x * 0.7071067811865475f));
}

// m16n8k16 row.col fp16 MMA with f32 accumulate (arch-stable, sm_80+)
__device__ __forceinline__ void mma16816(float* c, const uint32_t* a,
                                         uint32_t b0, uint32_t b1) {
    asm volatile(
        "mma.sync.aligned.m16n8k16.row.col.f32.f16.f16.f32 "
        "{%0,%1,%2,%3}, {%4,%5,%6,%7}, {%8,%9}, {%0,%1,%2,%3};"
        : "+f"(c[0]), "+f"(c[1]), "+f"(c[2]), "+f"(c[3])
        : "r"(a[0]), "r"(a[1]), "r"(a[2]), "r"(a[3]), "r"(b0), "r"(b1));
}

__device__ __forceinline__ uint32_t pack_h2(float lo, float hi) {
    __half2 h = __floats2half2_rn(lo, hi);
    return *reinterpret_cast<uint32_t*>(&h);
}

// ---------------------------------------------------------------------------
// Kernel 1: ONE block, 512 threads. Computes, for all 32 batches at once:
//   query MLP chain -> u, C; plus fp16 weight-fragment prep for k2.
// Dynamic smem: BUF0[4096] BUF1[4096] PART[16384] REDC[512]  (floats)
// ---------------------------------------------------------------------------
__global__ void __launch_bounds__(512) k1_precompute(
    const float* __restrict__ xq_all,
    const float* __restrict__ wx1,
    const float* __restrict__ wq1, const float* __restrict__ bq1,
    const float* __restrict__ wq2, const float* __restrict__ bq2,
    const float* __restrict__ wqp, const float* __restrict__ bqp,
    const float* __restrict__ wkp, const float* __restrict__ bkp,
    const float* __restrict__ wx2, const float* __restrict__ bx2)
{
    extern __shared__ float sm[];
    float* B0   = sm;               // [128][32]  (k-major, batch-minor)
    float* B1   = sm + 4096;        // [128][32]
    float* PART = sm + 8192;        // [4][128][32] (16B-swizzled)
    float* REDC = sm + 24576;       // [32][16]

    const int tid = threadIdx.x;

    // ---- fp16 weight fragments for k2 (independent of the chain) ----
    {
#pragma unroll
        for (int t = 0; t < 4; t++) {
            int s = tid + t * 512;
            int l  = s & 31;
            int ks = (s >> 5) & 3;
            int nt = s >> 7;
            int n  = nt * 8 + (l >> 2);
            int k0 = ks * 16 + (l & 3) * 2;
            float w0 = wx1[(k0 + 0) * DD + n];
            float w1 = wx1[(k0 + 1) * DD + n];
            float w8 = wx1[(k0 + 8) * DD + n];
            float w9 = wx1[(k0 + 9) * DD + n];
            unsigned long long p =
                (unsigned long long)pack_h2(w0, w1)
              | ((unsigned long long)pack_h2(w8, w9) << 32);
            g_wfrag[s] = p;
        }
    }

    // ---- stage A: G[i][b] = gelu(xq[b]*wq1[i] + bq1[i]) ----
#pragma unroll
    for (int s = 0; s < 8; s++) {
        int idx = tid + s * 512;
        int i = idx >> 5, b = idx & 31;
        B0[i * 32 + b] = gelu_exact(xq_all[b] * wq1[i] + bq1[i]);
    }
    __syncthreads();

    const int i  = tid & 127;
    const int kg = tid >> 7;      // 0..3

    // Generic stage: OUT[i][b] = sum_k w(k,i) * IN[k][b]  (+bias in combine)
    // colmajor: w = W[k*DD+i]; rowmajor: w = W[i*DD+k]
#define STAGE(INBUF, OUTBUF, W, ROWMAJOR, BIASPTR)                              \
    {                                                                           \
        float acc[32];                                                          \
        _Pragma("unroll")                                                       \
        for (int t = 0; t < 32; t++) acc[t] = 0.f;                              \
        _Pragma("unroll 4")                                                     \
        for (int kk = 0; kk < 32; kk++) {                                       \
            int k = kg * 32 + kk;                                               \
            float w = (ROWMAJOR) ? (W)[i * DD + k] : (W)[k * DD + i];           \
            const float4* row = reinterpret_cast<const float4*>((INBUF) + k*32);\
            _Pragma("unroll")                                                   \
            for (int bb = 0; bb < 8; bb++) {                                    \
                float4 g = row[bb];                                             \
                acc[bb*4+0] += g.x * w; acc[bb*4+1] += g.y * w;                 \
                acc[bb*4+2] += g.z * w; acc[bb*4+3] += g.w * w;                 \
            }                                                                   \
        }                                                                       \
        float4* prow = reinterpret_cast<float4*>(PART + (kg*128 + i) * 32);     \
        _Pragma("unroll")                                                       \
        for (int bb = 0; bb < 8; bb++)                                          \
            prow[bb ^ (i & 7)] =                                                \
                make_float4(acc[bb*4+0], acc[bb*4+1], acc[bb*4+2], acc[bb*4+3]);\
        __syncthreads();                                                        \
        _Pragma("unroll")                                                       \
        for (int s = 0; s < 8; s++) {                                           \
            int idx = tid + s * 512;                                            \
            int oi = idx >> 5, ob = idx & 31;                                   \
            int sw = (((ob >> 2) ^ (oi & 7)) << 2) + (ob & 3);                  \
            float v = PART[(0*128 + oi)*32 + sw] + PART[(1*128 + oi)*32 + sw]   \
                    + PART[(2*128 + oi)*32 + sw] + PART[(3*128 + oi)*32 + sw];  \
            if (BIASPTR) v += ((const float*)(BIASPTR))[oi];                    \
            (OUTBUF)[oi * 32 + ob] = v;                                         \
        }                                                                       \
        __syncthreads();                                                        \
    }

    STAGE(B0, B1, wq2, 0, bq2);   // h  = g@wq2+bq2      (B1 = h)
    STAGE(B1, B0, wqp, 0, bqp);   // q  = h@wqp+bqp      (B0 = q)
    STAGE(B0, B1, wkp, 1, (const float*)nullptr);  // t = wkp@q   (B1 = t)

    // stage E: u = wx2@t -> write g_u directly (keep B0=q, B1=t)
    {
        float acc[32];
#pragma unroll
        for (int t = 0; t < 32; t++) acc[t] = 0.f;
#pragma unroll 4
        for (int kk = 0; kk < 32; kk++) {
            int k = kg * 32 + kk;
            float w = wx2[i * DD + k];
            const float4* row = reinterpret_cast<const float4*>(B1 + k * 32);
#pragma unroll
            for (int bb = 0; bb < 8; bb++) {
                float4 g = row[bb];
                acc[bb*4+0] += g.x * w; acc[bb*4+1] += g.y * w;
                acc[bb*4+2] += g.z * w; acc[bb*4+3] += g.w * w;
            }
        }
        float4* prow = reinterpret_cast<float4*>(PART + (kg*128 + i) * 32);
#pragma unroll
        for (int bb = 0; bb < 8; bb++)
            prow[bb ^ (i & 7)] =
                make_float4(acc[bb*4+0], acc[bb*4+1], acc[bb*4+2], acc[bb*4+3]);
        __syncthreads();
#pragma unroll
        for (int s = 0; s < 8; s++) {
            int idx = tid + s * 512;
            int oi = idx >> 5, ob = idx & 31;
            int sw = (((ob >> 2) ^ (oi & 7)) << 2) + (ob & 3);
            float v = PART[(0*128 + oi)*32 + sw] + PART[(1*128 + oi)*32 + sw]
                    + PART[(2*128 + oi)*32 + sw] + PART[(3*128 + oi)*32 + sw];
            g_u[ob * DD + oi] = v;
        }
        __syncthreads();
    }

    // C[b] = sum_i bx2[i]*t[i][b] + bkp[i]*q[i][b]
    {
        int b = tid >> 4;
        int is = tid & 15;
        float a = 0.f;
#pragma unroll
        for (int t = 0; t < 8; t++) {
            int ii = is * 8 + t;
            a += bx2[ii] * B1[ii * 32 + b] + bkp[ii] * B0[ii * 32 + b];
        }
        REDC[b * 16 + is] = a;
        __syncthreads();
        if (tid < 32) {
            float s = 0.f;
#pragma unroll
            for (int t = 0; t < 16; t++) s += REDC[tid * 16 + t];
            g_C[tid] = s;
        }
    }
#undef STAGE
}

// ---------------------------------------------------------------------------
// Kernel 2 (dominant): single-product fp16 HMMA.
// Grid (NN/128, BB), 128 threads (4 warps). Tile M=128 items, N=128, K=64.
// A fragments direct from global (float2 -> fp16x2). B = prebuilt fragment
// buffer (straight copy to smem, 1 LDS.64 per k-step in mainloop).
// score_n = scale*(gelu(x_n@wx1+bx1) . u + C)
// ---------------------------------------------------------------------------
static constexpr int S_B   = 0;         // 16384 bytes
static constexpr int S_US  = 16384;
static constexpr int S_BXS = S_US + 512;
static constexpr int S_TOT = S_BXS + 512;

__global__ void __launch_bounds__(128) k2_scores_hmma(
    const float* __restrict__ x_items,
    const float* __restrict__ bx1)
{
    extern __shared__ char smem[];
    const int tid = threadIdx.x;
    const int wid = tid >> 5;
    const int lid = tid & 31;
    const int qr  = lid >> 2;   // quad row (0..7)
    const int qc  = lid & 3;    // quad col (0..3)
    const int b   = blockIdx.y;
    const int tile0 = blockIdx.x * 128;

    float* us  = reinterpret_cast<float*>(smem + S_US);
    float* bxs = reinterpret_cast<float*>(smem + S_BXS);
    us[tid]  = g_u[b * DD + tid];
    bxs[tid] = bx1[tid];
    const float Cs = g_C[b];

    // ---- B: straight copy of prebuilt fragment buffer (16 KB)
    {
        const uint4* gf = reinterpret_cast<const uint4*>(g_wfrag);
        uint4* bs = reinterpret_cast<uint4*>(smem + S_B);
#pragma unroll
        for (int j = 0; j < 8; j++) bs[tid + j * 128] = gf[tid + j * 128];
    }

    // ---- A fragments: direct from global, fp16 pack
    uint32_t A[2][4][4];
    {
        const float* xb = x_items + ((size_t)b * NN + (size_t)tile0) * IDM;
#pragma unroll
        for (int mt = 0; mt < 2; mt++) {
            int r0 = wid * 32 + mt * 16 + qr;
#pragma unroll
            for (int ks = 0; ks < 4; ks++) {
                int k0 = ks * 16 + qc * 2;
                float2 v00 = *reinterpret_cast<const float2*>(xb + (size_t)r0 * IDM + k0);
                float2 v10 = *reinterpret_cast<const float2*>(xb + (size_t)(r0 + 8) * IDM + k0);
                float2 v01 = *reinterpret_cast<const float2*>(xb + (size_t)r0 * IDM + k0 + 8);
                float2 v11 = *reinterpret_cast<const float2*>(xb + (size_t)(r0 + 8) * IDM + k0 + 8);
                A[mt][ks][0] = pack_h2(v00.x, v00.y);
                A[mt][ks][1] = pack_h2(v10.x, v10.y);
                A[mt][ks][2] = pack_h2(v01.x, v01.y);
                A[mt][ks][3] = pack_h2(v11.x, v11.y);
            }
        }
    }
    __syncthreads();

    // ---- Mainloop over 16 n-tiles of 8 columns
    float sc[2][2] = {{0.f, 0.f}, {0.f, 0.f}};   // [mtile][row-half]
#pragma unroll 1
    for (int nt = 0; nt < 16; nt++) {
        float c0[4] = {0.f, 0.f, 0.f, 0.f};
        float c1[4] = {0.f, 0.f, 0.f, 0.f};
#pragma unroll
        for (int ks = 0; ks < 4; ks++) {
            unsigned long long bb = *reinterpret_cast<const unsigned long long*>(
                smem + S_B + (((nt * 4 + ks) * 32) + lid) * 8);
            uint32_t b0 = (uint32_t)bb;
            uint32_t b1 = (uint32_t)(bb >> 32);
            mma16816(c0, A[0][ks], b0, b1);
            mma16816(c1, A[1][ks], b0, b1);
        }
        int n0 = nt * 8 + qc * 2;
        float2 bias = *reinterpret_cast<const float2*>(&bxs[n0]);
        float2 uu   = *reinterpret_cast<const float2*>(&us[n0]);
        sc[0][0] += gelu_exact(c0[0] + bias.x) * uu.x + gelu_exact(c0[1] + bias.y) * uu.y;
        sc[0][1] += gelu_exact(c0[2] + bias.x) * uu.x + gelu_exact(c0[3] + bias.y) * uu.y;
        sc[1][0] += gelu_exact(c1[0] + bias.x) * uu.x + gelu_exact(c1[1] + bias.y) * uu.y;
        sc[1][1] += gelu_exact(c1[2] + bias.x) * uu.x + gelu_exact(c1[3] + bias.y) * uu.y;
    }

    // ---- quad reduction (lanes sharing qr) and store
#pragma unroll
    for (int mt = 0; mt < 2; mt++) {
#pragma unroll
        for (int h = 0; h < 2; h++) {
            float v = sc[mt][h];
            v += __shfl_xor_sync(0xffffffffu, v, 1);
            v += __shfl_xor_sync(0xffffffffu, v, 2);
            sc[mt][h] = v;
        }
    }
    if (qc == 0) {
#pragma unroll
        for (int mt = 0; mt < 2; mt++) {
#pragma unroll
            for (int h = 0; h < 2; h++) {
                int item = tile0 + wid * 32 + mt * 16 + h * 8 + qr;
                g_scores[b * NN + item] =
                    0.08838834764831845f * (sc[mt][h] + Cs);
            }
        }
    }
}

// ---------------------------------------------------------------------------
// Kernel 3: sparsemax (Michelot + bisection + exact refine) + sparse readout
// + head MLP. 32 blocks x 1024 threads, 2 barriers per reduction round.
// ---------------------------------------------------------------------------
__global__ void __launch_bounds__(1024) k3_sparsemax_out(
    const float* __restrict__ x_items,
    const float* __restrict__ wx1, const float* __restrict__ bx1,
    const float* __restrict__ wx2, const float* __restrict__ bx2,
    const float* __restrict__ wvp, const float* __restrict__ bvp,
    const float* __restrict__ wp1, const float* __restrict__ bp1,
    const float* __restrict__ wp2, const float* __restrict__ bp2,
    float* __restrict__ out)
{
    __shared__ float sP[32];
    __shared__ float sP2[32];
    __shared__ float bc[2];
    __shared__ float accg[DD];
    __shared__ float buf1[DD];
    __shared__ float buf2[DD];

    const int tid  = threadIdx.x;
    const int b    = blockIdx.x;
    const int lane = tid & 31;
    const int wid  = tid >> 5;
    const float* sc = g_scores + b * NN;

    if (tid < DD) accg[tid] = 0.f;

    float z[16];
#pragma unroll
    for (int j = 0; j < 16; j++) z[j] = sc[tid + j * 1024];

    // ---- block max (2 barriers) ----
    float m = z[0];
#pragma unroll
    for (int j = 1; j < 16; j++) m = fmaxf(m, z[j]);
#pragma unroll
    for (int o = 16; o > 0; o >>= 1) m = fmaxf(m, __shfl_xor_sync(0xffffffffu, m, o));
    if (lane == 0) sP[wid] = m;
    __syncthreads();
    if (wid == 0) {
        float v = sP[lane];
#pragma unroll
        for (int o = 16; o > 0; o >>= 1) v = fmaxf(v, __shfl_xor_sync(0xffffffffu, v, o));
        if (lane == 0) bc[0] = v;
    }
    __syncthreads();
    const float zmax = bc[0];

    // ---- Michelot fixed-point, 8 rounds (2 barriers each)
    float tau = zmax - 1.0f;
#pragma unroll 1
    for (int it = 0; it < 8; it++) {
        float s = 0.f, c = 0.f;
#pragma unroll
        for (int j = 0; j < 16; j++) {
            if (z[j] > tau) { s += z[j]; c += 1.f; }
        }
#pragma unroll
        for (int o = 16; o > 0; o >>= 1) {
            s += __shfl_xor_sync(0xffffffffu, s, o);
            c += __shfl_xor_sync(0xffffffffu, c, o);
        }
        if (lane == 0) { sP[wid] = s; sP2[wid] = c; }
        __syncthreads();
        if (wid == 0) {
            float s2 = sP[lane], c2 = sP2[lane];
#pragma unroll
            for (int o = 16; o > 0; o >>= 1) {
                s2 += __shfl_xor_sync(0xffffffffu, s2, o);
                c2 += __shfl_xor_sync(0xffffffffu, c2, o);
            }
            if (lane == 0) bc[0] = (s2 - 1.0f) / c2;
        }
        __syncthreads();
        tau = bc[0];
    }

    // ---- bisection polish in [tau, zmax], 18 rounds (2 barriers each)
    float lo = tau, hi = zmax;
#pragma unroll 1
    for (int it = 0; it < 18; it++) {
        float mid = 0.5f * (lo + hi);
        float s = 0.f;
#pragma unroll
        for (int j = 0; j < 16; j++) s += fmaxf(z[j] - mid, 0.f);
#pragma unroll
        for (int o = 16; o > 0; o >>= 1) s += __shfl_xor_sync(0xffffffffu, s, o);
        if (lane == 0) sP[wid] = s;
        __syncthreads();
        if (wid == 0) {
            float s2 = sP[lane];
#pragma unroll
            for (int o = 16; o > 0; o >>= 1) s2 += __shfl_xor_sync(0xffffffffu, s2, o);
            if (lane == 0) bc[0] = s2;
        }
        __syncthreads();
        if (bc[0] > 1.0f) lo = mid; else hi = mid;
    }
    const float tau0 = 0.5f * (lo + hi);

    // ---- exact refine: support {z > tau0}, tau = (S-1)/k
    {
        float s = 0.f, c = 0.f;
#pragma unroll
        for (int j = 0; j < 16; j++) {
            if (z[j] > tau0) { s += z[j]; c += 1.f; }
        }
#pragma unroll
        for (int o = 16; o > 0; o >>= 1) {
            s += __shfl_xor_sync(0xffffffffu, s, o);
            c += __shfl_xor_sync(0xffffffffu, c, o);
        }
        if (lane == 0) { sP[wid] = s; sP2[wid] = c; }
        __syncthreads();
        if (wid == 0) {
            float s2 = sP[lane], c2 = sP2[lane];
#pragma unroll
            for (int o = 16; o > 0; o >>= 1) {
                s2 += __shfl_xor_sync(0xffffffffu, s2, o);
                c2 += __shfl_xor_sync(0xffffffffu, c2, o);
            }
            if (lane == 0) bc[1] = (s2 - 1.0f) / c2;
        }
        __syncthreads();
    }
    const float tauF = bc[1];

    // ---- sparse accumulation: Gbar = sum_n attn_n * gelu(x_n@wx1+bx1)
#pragma unroll 1
    for (int j = 0; j < 16; j++) {
        float zz = z[j];
        unsigned msk = __ballot_sync(0xffffffffu, zz > tau0);
        while (msk) {
            int jb = __ffs(msk) - 1;
            msk &= msk - 1;
            float w = fmaxf(__shfl_sync(0xffffffffu, zz, jb) - tauF, 0.f);
            int item = wid * 32 + j * 1024 + jb;
            const float* xr = x_items + ((size_t)b * NN + (size_t)item) * IDM;
            float x0 = xr[2 * lane], x1 = xr[2 * lane + 1];
            float a0 = bx1[lane];
            float a1 = bx1[lane + 32];
            float a2 = bx1[lane + 64];
            float a3 = bx1[lane + 96];
#pragma unroll
            for (int k = 0; k < IDM; k++) {
                float xv = __shfl_sync(0xffffffffu, (k & 1) ? x1 : x0, k >> 1);
                a0 += xv * wx1[k * DD + lane];
                a1 += xv * wx1[k * DD + lane + 32];
                a2 += xv * wx1[k * DD + lane + 64];
                a3 += xv * wx1[k * DD + lane + 96];
            }
            atomicAdd(&accg[lane],      w * gelu_exact(a0));
            atomicAdd(&accg[lane + 32], w * gelu_exact(a1));
            atomicAdd(&accg[lane + 64], w * gelu_exact(a2));
            atomicAdd(&accg[lane + 96], w * gelu_exact(a3));
        }
    }
    __syncthreads();

    // ---- head MLP (first 128 threads, 4-way ILP)
    if (tid < DD) {
        float a0 = 0.f, a1 = 0.f, a2 = 0.f, a3 = 0.f;
#pragma unroll 8
        for (int k = 0; k < DD; k += 4) {
            a0 += accg[k + 0] * wx2[(k + 0) * DD + tid];
            a1 += accg[k + 1] * wx2[(k + 1) * DD + tid];
            a2 += accg[k + 2] * wx2[(k + 2) * DD + tid];
            a3 += accg[k + 3] * wx2[(k + 3) * DD + tid];
        }
        buf1[tid] = (a0 + a1) + (a2 + a3) + bx2[tid];
    }
    __syncthreads();
    if (tid < DD) {
        float a0 = 0.f, a1 = 0.f, a2 = 0.f, a3 = 0.f;
#pragma unroll 8
        for (int k = 0; k < DD; k += 4) {
            a0 += buf1[k + 0] * wvp[(k + 0) * DD + tid];
            a1 += buf1[k + 1] * wvp[(k + 1) * DD + tid];
            a2 += buf1[k + 2] * wvp[(k + 2) * DD + tid];
            a3 += buf1[k + 3] * wvp[(k + 3) * DD + tid];
        }
        buf2[tid] = (a0 + a1) + (a2 + a3) + bvp[tid];
    }
    __syncthreads();
    if (tid < DD) {
        float a0 = 0.f, a1 = 0.f, a2 = 0.f, a3 = 0.f;
#pragma unroll 8
        for (int k = 0; k < DD; k += 4) {
            a0 += buf2[k + 0] * wp1[(k + 0) * DD + tid];
            a1 += buf2[k + 1] * wp1[(k + 1) * DD + tid];
            a2 += buf2[k + 2] * wp1[(k + 2) * DD + tid];
            a3 += buf2[k + 3] * wp1[(k + 3) * DD + tid];
        }
        buf1[tid] = gelu_exact((a0 + a1) + (a2 + a3) + bp1[tid]);
    }
    __syncthreads();
    if (tid < NCLS) {
        float o = bp2[tid];
#pragma unroll 8
        for (int k = 0; k < DD; k++) o += buf1[k] * wp2[k * NCLS + tid];
        out[b * NCLS + tid] = o;
    }
}

// ---------------------------------------------------------------------------
extern "C" void kernel_launch(void* const* d_in, const int* in_sizes, int n_in,
                              void* d_out, int out_size)
{
    const float* x_items = (const float*)d_in[0];
    const float* x_query = (const float*)d_in[1];
    const float* wx1 = (const float*)d_in[2];
    const float* bx1 = (const float*)d_in[3];
    const float* wx2 = (const float*)d_in[4];
    const float* bx2 = (const float*)d_in[5];
    const float* wq1 = (const float*)d_in[6];
    const float* bq1 = (const float*)d_in[7];
    const float* wq2 = (const float*)d_in[8];
    const float* bq2 = (const float*)d_in[9];
    const float* wqp = (const float*)d_in[10];
    const float* bqp = (const float*)d_in[11];
    const float* wkp = (const float*)d_in[12];
    const float* bkp = (const float*)d_in[13];
    const float* wvp = (const float*)d_in[14];
    const float* bvp = (const float*)d_in[15];
    const float* wp1 = (const float*)d_in[16];
    const float* bp1 = (const float*)d_in[17];
    const float* wp2 = (const float*)d_in[18];
    const float* bp2 = (const float*)d_in[19];
    float* out = (float*)d_out;

    const int K1_SMEM = (4096 + 4096 + 16384 + 512) * 4;   // 100,352 B
    cudaFuncSetAttribute(k1_precompute,
                         cudaFuncAttributeMaxDynamicSharedMemorySize, K1_SMEM);
    cudaFuncSetAttribute(k2_scores_hmma,
                         cudaFuncAttributeMaxDynamicSharedMemorySize, S_TOT);

    k1_precompute<<<1, 512, K1_SMEM>>>(x_query, wx1, wq1, bq1, wq2, bq2,
                                       wqp, bqp, wkp, bkp, wx2, bx2);

    dim3 g2(NN / 128, BB);
    k2_scores_hmma<<<g2, 128, S_TOT>>>(x_items, bx1);

    k3_sparsemax_out<<<BB, 1024>>>(x_items, wx1, bx1, wx2, bx2,
                                   wvp, bvp, wp1, bp1, wp2, bp2, out);
}

// round 10
// speedup vs baseline: 1.6577x; 1.0370x over previous
#include <cuda_runtime.h>
#include <cuda_fp16.h>
#include <cstdint>

#define BB   32
#define NN   16384
#define DD   128
#define IDM  64
#define NCLS 10

// ---------------------------------------------------------------------------
// Scratch (device globals — no allocation allowed)
// ---------------------------------------------------------------------------
__device__ float g_scores[BB * NN];
__device__ float g_u[BB * DD];
__device__ float g_C[BB];
__device__ __align__(16) unsigned long long g_wfrag[2048];
// precomposed matrices / vectors
__device__ float g_M1[DD * DD];    // M1[k,m] = sum_p wq2[k,p] wqp[p,m]
__device__ float g_A2t[DD * DD];   // A2t[m,i] = A2[i,m] = sum_j wx2[i,j] wkp[j,m]
__device__ float g_M3[DD * DD];    // M3[k,i] = sum_m M1[k,m] A2[i,m]
__device__ float g_v[DD];          // v[j] = sum_i bx2[i] wkp[i,j] + bkp[j]
__device__ float g_cq[DD];         // cq[m] = sum_p bq2[p] wqp[p,m] + bqp[m]
__device__ float g_vecC[DD];       // vecC[k] = sum_m M1[k,m] v[m]
__device__ float g_cu[DD];         // cu[i] = sum_m A2[i,m] cq[m]
__device__ float g_c0;             // c0 = sum_m cq[m] v[m]

__device__ __forceinline__ float gelu_exact(float x) {
    return 0.5f * x * (1.0f + erff(x * 0.7071067811865475f));
}

__device__ __forceinline__ void mma16816(float* c, const uint32_t* a,
                                         uint32_t b0, uint32_t b1) {
    asm volatile(
        "mma.sync.aligned.m16n8k16.row.col.f32.f16.f16.f32 "
        "{%0,%1,%2,%3}, {%4,%5,%6,%7}, {%8,%9}, {%0,%1,%2,%3};"
        : "+f"(c[0]), "+f"(c[1]), "+f"(c[2]), "+f"(c[3])
        : "r"(a[0]), "r"(a[1]), "r"(a[2]), "r"(a[3]), "r"(b0), "r"(b1));
}

__device__ __forceinline__ uint32_t pack_h2(float lo, float hi) {
    __half2 h = __floats2half2_rn(lo, hi);
    return *reinterpret_cast<uint32_t*>(&h);
}

// ---------------------------------------------------------------------------
// k1a: independent precomputes. 274 blocks x 128 threads.
//  blocks 0..127   : M1 row k
//  blocks 128..255 : A2 row i -> stored transposed in g_A2t
//  blocks 256..271 : fp16 weight fragments for k2
//  block  272      : v
//  block  273      : cq
// ---------------------------------------------------------------------------
__global__ void __launch_bounds__(128) k1a(
    const float* __restrict__ wx1,
    const float* __restrict__ wq2, const float* __restrict__ bq2,
    const float* __restrict__ wqp, const float* __restrict__ bqp,
    const float* __restrict__ wkp, const float* __restrict__ bkp,
    const float* __restrict__ wx2, const float* __restrict__ bx2)
{
    const int bid = blockIdx.x;
    const int t   = threadIdx.x;

    if (bid < 128) {                       // M1[k,m], k=bid, thread=m
        const int k = bid;
        float a0 = 0.f, a1 = 0.f;
#pragma unroll 8
        for (int p = 0; p < DD; p += 2) {
            a0 += wq2[k * DD + p + 0] * wqp[(p + 0) * DD + t];
            a1 += wq2[k * DD + p + 1] * wqp[(p + 1) * DD + t];
        }
        g_M1[k * DD + t] = a0 + a1;
    } else if (bid < 256) {                // A2[i,m], i=bid-128, thread=m
        const int i = bid - 128;
        float a0 = 0.f, a1 = 0.f;
#pragma unroll 8
        for (int j = 0; j < DD; j += 2) {
            a0 += wx2[i * DD + j + 0] * wkp[(j + 0) * DD + t];
            a1 += wx2[i * DD + j + 1] * wkp[(j + 1) * DD + t];
        }
        g_A2t[t * DD + i] = a0 + a1;       // transposed store
    } else if (bid < 272) {                // weight fragments
        int s = (bid - 256) * 128 + t;     // 0..2047
        int l  = s & 31;
        int ks = (s >> 5) & 3;
        int nt = s >> 7;
        int n  = nt * 8 + (l >> 2);
        int k0 = ks * 16 + (l & 3) * 2;
        float w0 = wx1[(k0 + 0) * DD + n];
        float w1 = wx1[(k0 + 1) * DD + n];
        float w8 = wx1[(k0 + 8) * DD + n];
        float w9 = wx1[(k0 + 9) * DD + n];
        g_wfrag[s] = (unsigned long long)pack_h2(w0, w1)
                   | ((unsigned long long)pack_h2(w8, w9) << 32);
    } else if (bid == 272) {               // v[j], thread=j
        float a = 0.f;
#pragma unroll 8
        for (int i = 0; i < DD; i++) a += bx2[i] * wkp[i * DD + t];
        g_v[t] = a + bkp[t];
    } else {                               // cq[m], thread=m
        float a = 0.f;
#pragma unroll 8
        for (int p = 0; p < DD; p++) a += bq2[p] * wqp[p * DD + t];
        g_cq[t] = a + bqp[t];
    }
}

// ---------------------------------------------------------------------------
// k1b: M3 = M1 @ A2t-composition, vecC, cu, c0.  130 blocks x 128.
// ---------------------------------------------------------------------------
__global__ void __launch_bounds__(128) k1b()
{
    const int bid = blockIdx.x;
    const int t   = threadIdx.x;
    __shared__ float sv[DD];
    __shared__ float red[4];

    if (bid < 128) {                       // M3[k,i] = sum_m M1[k,m] A2t[m,i]
        const int k = bid;
        float a0 = 0.f, a1 = 0.f;
#pragma unroll 8
        for (int m = 0; m < DD; m += 2) {
            a0 += g_M1[k * DD + m + 0] * g_A2t[(m + 0) * DD + t];
            a1 += g_M1[k * DD + m + 1] * g_A2t[(m + 1) * DD + t];
        }
        g_M3[k * DD + t] = a0 + a1;
    } else if (bid == 128) {               // vecC[k] + c0
        sv[t] = g_v[t];
        __syncthreads();
        float a = 0.f;
#pragma unroll 8
        for (int m = 0; m < DD; m++) a += g_M1[t * DD + m] * sv[m];
        g_vecC[t] = a;
        // c0 = sum cq[m] v[m]
        float p = g_cq[t] * sv[t];
#pragma unroll
        for (int o = 16; o > 0; o >>= 1) p += __shfl_xor_sync(0xffffffffu, p, o);
        if ((t & 31) == 0) red[t >> 5] = p;
        __syncthreads();
        if (t == 0) g_c0 = red[0] + red[1] + red[2] + red[3];
    } else {                               // cu[i] = sum_m A2t[m,i] cq[m]
        sv[t] = g_cq[t];
        __syncthreads();
        float a0 = 0.f, a1 = 0.f;
#pragma unroll 8
        for (int m = 0; m < DD; m += 2) {
            a0 += g_A2t[(m + 0) * DD + t] * sv[m + 0];
            a1 += g_A2t[(m + 1) * DD + t] * sv[m + 1];
        }
        g_cu[t] = a0 + a1;
    }
}

// ---------------------------------------------------------------------------
// k1c: per-batch finals. 32 blocks x 128. u = g@M3 + cu; C = g.vecC + c0.
// ---------------------------------------------------------------------------
__global__ void __launch_bounds__(128) k1c(
    const float* __restrict__ xq_all,
    const float* __restrict__ wq1, const float* __restrict__ bq1)
{
    __shared__ float sg[DD];
    __shared__ float red[4];
    const int b = blockIdx.x;
    const int t = threadIdx.x;

    sg[t] = gelu_exact(xq_all[b] * wq1[t] + bq1[t]);
    __syncthreads();

    float a0 = 0.f, a1 = 0.f;
#pragma unroll 8
    for (int k = 0; k < DD; k += 2) {
        a0 += sg[k + 0] * g_M3[(k + 0) * DD + t];
        a1 += sg[k + 1] * g_M3[(k + 1) * DD + t];
    }
    g_u[b * DD + t] = a0 + a1 + g_cu[t];

    float p = sg[t] * g_vecC[t];
#pragma unroll
    for (int o = 16; o > 0; o >>= 1) p += __shfl_xor_sync(0xffffffffu, p, o);
    if ((t & 31) == 0) red[t >> 5] = p;
    __syncthreads();
    if (t == 0) g_C[b] = red[0] + red[1] + red[2] + red[3] + g_c0;
}

// ---------------------------------------------------------------------------
// Kernel 2 (dominant): single-product fp16 HMMA.
// Grid (NN/256, BB), 256 threads (8 warps). 256 items x 128 hidden, K=64.
// ---------------------------------------------------------------------------
static constexpr int S_B   = 0;         // 16384 bytes
static constexpr int S_US  = 16384;
static constexpr int S_BXS = S_US + 512;
static constexpr int S_TOT = S_BXS + 512;

__global__ void __launch_bounds__(256) k2_scores_hmma(
    const float* __restrict__ x_items,
    const float* __restrict__ bx1)
{
    extern __shared__ char smem[];
    const int tid = threadIdx.x;
    const int wid = tid >> 5;
    const int lid = tid & 31;
    const int qr  = lid >> 2;
    const int qc  = lid & 3;
    const int b   = blockIdx.y;
    const int tile0 = blockIdx.x * 256;

    float* us  = reinterpret_cast<float*>(smem + S_US);
    float* bxs = reinterpret_cast<float*>(smem + S_BXS);
    if (tid < DD) {
        us[tid]  = g_u[b * DD + tid];
        bxs[tid] = bx1[tid];
    }
    const float Cs = g_C[b];

    // ---- B: straight copy of prebuilt fragment buffer (16 KB)
    {
        const uint4* gf = reinterpret_cast<const uint4*>(g_wfrag);
        uint4* bs = reinterpret_cast<uint4*>(smem + S_B);
#pragma unroll
        for (int j = 0; j < 4; j++) bs[tid + j * 256] = gf[tid + j * 256];
    }

    // ---- A fragments: direct from global, fp16 pack
    uint32_t A[2][4][4];
    {
        const float* xb = x_items + ((size_t)b * NN + (size_t)tile0) * IDM;
#pragma unroll
        for (int mt = 0; mt < 2; mt++) {
            int r0 = wid * 32 + mt * 16 + qr;
#pragma unroll
            for (int ks = 0; ks < 4; ks++) {
                int k0 = ks * 16 + qc * 2;
                float2 v00 = *reinterpret_cast<const float2*>(xb + (size_t)r0 * IDM + k0);
                float2 v10 = *reinterpret_cast<const float2*>(xb + (size_t)(r0 + 8) * IDM + k0);
                float2 v01 = *reinterpret_cast<const float2*>(xb + (size_t)r0 * IDM + k0 + 8);
                float2 v11 = *reinterpret_cast<const float2*>(xb + (size_t)(r0 + 8) * IDM + k0 + 8);
                A[mt][ks][0] = pack_h2(v00.x, v00.y);
                A[mt][ks][1] = pack_h2(v10.x, v10.y);
                A[mt][ks][2] = pack_h2(v01.x, v01.y);
                A[mt][ks][3] = pack_h2(v11.x, v11.y);
            }
        }
    }
    __syncthreads();

    // ---- Mainloop over 16 n-tiles of 8 columns
    float sc[2][2] = {{0.f, 0.f}, {0.f, 0.f}};
#pragma unroll 1
    for (int nt = 0; nt < 16; nt++) {
        float c0[4] = {0.f, 0.f, 0.f, 0.f};
        float c1[4] = {0.f, 0.f, 0.f, 0.f};
#pragma unroll
        for (int ks = 0; ks < 4; ks++) {
            unsigned long long bb = *reinterpret_cast<const unsigned long long*>(
                smem + S_B + (((nt * 4 + ks) * 32) + lid) * 8);
            uint32_t b0 = (uint32_t)bb;
            uint32_t b1 = (uint32_t)(bb >> 32);
            mma16816(c0, A[0][ks], b0, b1);
            mma16816(c1, A[1][ks], b0, b1);
        }
        int n0 = nt * 8 + qc * 2;
        float2 bias = *reinterpret_cast<const float2*>(&bxs[n0]);
        float2 uu   = *reinterpret_cast<const float2*>(&us[n0]);
        sc[0][0] += gelu_exact(c0[0] + bias.x) * uu.x + gelu_exact(c0[1] + bias.y) * uu.y;
        sc[0][1] += gelu_exact(c0[2] + bias.x) * uu.x + gelu_exact(c0[3] + bias.y) * uu.y;
        sc[1][0] += gelu_exact(c1[0] + bias.x) * uu.x + gelu_exact(c1[1] + bias.y) * uu.y;
        sc[1][1] += gelu_exact(c1[2] + bias.x) * uu.x + gelu_exact(c1[3] + bias.y) * uu.y;
    }

#pragma unroll
    for (int mt = 0; mt < 2; mt++) {
#pragma unroll
        for (int h = 0; h < 2; h++) {
            float v = sc[mt][h];
            v += __shfl_xor_sync(0xffffffffu, v, 1);
            v += __shfl_xor_sync(0xffffffffu, v, 2);
            sc[mt][h] = v;
        }
    }
    if (qc == 0) {
#pragma unroll
        for (int mt = 0; mt < 2; mt++) {
#pragma unroll
            for (int h = 0; h < 2; h++) {
                int item = tile0 + wid * 32 + mt * 16 + h * 8 + qr;
                g_scores[b * NN + item] =
                    0.08838834764831845f * (sc[mt][h] + Cs);
            }
        }
    }
}

// ---------------------------------------------------------------------------
// Kernel 3: sparsemax via pure Michelot (20 rounds, 1 barrier each, per-round
// shared atomic slots) + sparse readout + head MLP. 32 blocks x 1024.
// ---------------------------------------------------------------------------
#define MICH_ROUNDS 20

__global__ void __launch_bounds__(1024) k3_sparsemax_out(
    const float* __restrict__ x_items,
    const float* __restrict__ wx1, const float* __restrict__ bx1,
    const float* __restrict__ wx2, const float* __restrict__ bx2,
    const float* __restrict__ wvp, const float* __restrict__ bvp,
    const float* __restrict__ wp1, const float* __restrict__ bp1,
    const float* __restrict__ wp2, const float* __restrict__ bp2,
    float* __restrict__ out)
{
    __shared__ float redS[MICH_ROUNDS];
    __shared__ float redK[MICH_ROUNDS];
    __shared__ float sM[32];
    __shared__ float accg[DD];
    __shared__ float buf1[DD];
    __shared__ float buf2[DD];

    const int tid  = threadIdx.x;
    const int b    = blockIdx.x;
    const int lane = tid & 31;
    const int wid  = tid >> 5;
    const float* sc = g_scores + b * NN;

    if (tid < MICH_ROUNDS) { redS[tid] = 0.f; redK[tid] = 0.f; }
    if (tid < DD) accg[tid] = 0.f;

    float z[16];
#pragma unroll
    for (int j = 0; j < 16; j++) z[j] = sc[tid + j * 1024];

    // ---- block max (1 barrier) ----
    float m = z[0];
#pragma unroll
    for (int j = 1; j < 16; j++) m = fmaxf(m, z[j]);
#pragma unroll
    for (int o = 16; o > 0; o >>= 1) m = fmaxf(m, __shfl_xor_sync(0xffffffffu, m, o));
    if (lane == 0) sM[wid] = m;
    __syncthreads();
    float zmax = sM[0];
#pragma unroll
    for (int j = 1; j < 32; j++) zmax = fmaxf(zmax, sM[j]);

    // ---- Michelot: tau <- (sum_{z>tau} z - 1)/count, monotone from below.
    // Fixed point is the exact sparsemax threshold (S-1)/k.
    float tau = zmax - 1.0f;
#pragma unroll 1
    for (int r = 0; r < MICH_ROUNDS; r++) {
        float s = 0.f, c = 0.f;
#pragma unroll
        for (int j = 0; j < 16; j++) {
            if (z[j] > tau) { s += z[j]; c += 1.f; }
        }
#pragma unroll
        for (int o = 16; o > 0; o >>= 1) {
            s += __shfl_xor_sync(0xffffffffu, s, o);
            c += __shfl_xor_sync(0xffffffffu, c, o);
        }
        if (lane == 0) {
            atomicAdd(&redS[r], s);
            atomicAdd(&redK[r], c);
        }
        __syncthreads();
        tau = (redS[r] - 1.0f) / redK[r];   // identical in all threads
    }

    // ---- sparse accumulation: Gbar = sum_n attn_n * gelu(x_n@wx1+bx1)
#pragma unroll 1
    for (int j = 0; j < 16; j++) {
        float zz = z[j];
        unsigned msk = __ballot_sync(0xffffffffu, zz > tau);
        while (msk) {
            int jb = __ffs(msk) - 1;
            msk &= msk - 1;
            float w = __shfl_sync(0xffffffffu, zz, jb) - tau;
            int item = wid * 32 + j * 1024 + jb;
            const float* xr = x_items + ((size_t)b * NN + (size_t)item) * IDM;
            float x0 = xr[2 * lane], x1 = xr[2 * lane + 1];
            float a0 = bx1[lane];
            float a1 = bx1[lane + 32];
            float a2 = bx1[lane + 64];
            float a3 = bx1[lane + 96];
#pragma unroll
            for (int k = 0; k < IDM; k++) {
                float xv = __shfl_sync(0xffffffffu, (k & 1) ? x1 : x0, k >> 1);
                a0 += xv * wx1[k * DD + lane];
                a1 += xv * wx1[k * DD + lane + 32];
                a2 += xv * wx1[k * DD + lane + 64];
                a3 += xv * wx1[k * DD + lane + 96];
            }
            atomicAdd(&accg[lane],      w * gelu_exact(a0));
            atomicAdd(&accg[lane + 32], w * gelu_exact(a1));
            atomicAdd(&accg[lane + 64], w * gelu_exact(a2));
            atomicAdd(&accg[lane + 96], w * gelu_exact(a3));
        }
    }
    __syncthreads();

    // ---- head MLP (first 128 threads, 4-way ILP)
    if (tid < DD) {
        float a0 = 0.f, a1 = 0.f, a2 = 0.f, a3 = 0.f;
#pragma unroll 8
        for (int k = 0; k < DD; k += 4) {
            a0 += accg[k + 0] * wx2[(k + 0) * DD + tid];
            a1 += accg[k + 1] * wx2[(k + 1) * DD + tid];
            a2 += accg[k + 2] * wx2[(k + 2) * DD + tid];
            a3 += accg[k + 3] * wx2[(k + 3) * DD + tid];
        }
        buf1[tid] = (a0 + a1) + (a2 + a3) + bx2[tid];
    }
    __syncthreads();
    if (tid < DD) {
        float a0 = 0.f, a1 = 0.f, a2 = 0.f, a3 = 0.f;
#pragma unroll 8
        for (int k = 0; k < DD; k += 4) {
            a0 += buf1[k + 0] * wvp[(k + 0) * DD + tid];
            a1 += buf1[k + 1] * wvp[(k + 1) * DD + tid];
            a2 += buf1[k + 2] * wvp[(k + 2) * DD + tid];
            a3 += buf1[k + 3] * wvp[(k + 3) * DD + tid];
        }
        buf2[tid] = (a0 + a1) + (a2 + a3) + bvp[tid];
    }
    __syncthreads();
    if (tid < DD) {
        float a0 = 0.f, a1 = 0.f, a2 = 0.f, a3 = 0.f;
#pragma unroll 8
        for (int k = 0; k < DD; k += 4) {
            a0 += buf2[k + 0] * wp1[(k + 0) * DD + tid];
            a1 += buf2[k + 1] * wp1[(k + 1) * DD + tid];
            a2 += buf2[k + 2] * wp1[(k + 2) * DD + tid];
            a3 += buf2[k + 3] * wp1[(k + 3) * DD + tid];
        }
        buf1[tid] = gelu_exact((a0 + a1) + (a2 + a3) + bp1[tid]);
    }
    __syncthreads();
    if (tid < NCLS) {
        float o = bp2[tid];
#pragma unroll 8
        for (int k = 0; k < DD; k++) o += buf1[k] * wp2[k * NCLS + tid];
        out[b * NCLS + tid] = o;
    }
}

// ---------------------------------------------------------------------------
extern "C" void kernel_launch(void* const* d_in, const int* in_sizes, int n_in,
                              void* d_out, int out_size)
{
    const float* x_items = (const float*)d_in[0];
    const float* x_query = (const float*)d_in[1];
    const float* wx1 = (const float*)d_in[2];
    const float* bx1 = (const float*)d_in[3];
    const float* wx2 = (const float*)d_in[4];
    const float* bx2 = (const float*)d_in[5];
    const float* wq1 = (const float*)d_in[6];
    const float* bq1 = (const float*)d_in[7];
    const float* wq2 = (const float*)d_in[8];
    const float* bq2 = (const float*)d_in[9];
    const float* wqp = (const float*)d_in[10];
    const float* bqp = (const float*)d_in[11];
    const float* wkp = (const float*)d_in[12];
    const float* bkp = (const float*)d_in[13];
    const float* wvp = (const float*)d_in[14];
    const float* bvp = (const float*)d_in[15];
    const float* wp1 = (const float*)d_in[16];
    const float* bp1 = (const float*)d_in[17];
    const float* wp2 = (const float*)d_in[18];
    const float* bp2 = (const float*)d_in[19];
    float* out = (float*)d_out;

    cudaFuncSetAttribute(k2_scores_hmma,
                         cudaFuncAttributeMaxDynamicSharedMemorySize, S_TOT);

    k1a<<<274, 128>>>(wx1, wq2, bq2, wqp, bqp, wkp, bkp, wx2, bx2);
    k1b<<<130, 128>>>();
    k1c<<<BB, 128>>>(x_query, wq1, bq1);

    dim3 g2(NN / 256, BB);
    k2_scores_hmma<<<g2, 256, S_TOT>>>(x_items, bx1);

    k3_sparsemax_out<<<BB, 1024>>>(x_items, wx1, bx1, wx2, bx2,
                                   wvp, bvp, wp1, bp1, wp2, bp2, out);
}

// round 11
// speedup vs baseline: 2.7113x; 1.6355x over previous
#include <cuda_runtime.h>
#include <cuda_fp16.h>
#include <cstdint>

#define BB   32
#define NN   16384
#define DD   128
#define IDM  64
#define NCLS 10

// ---------------------------------------------------------------------------
// Scratch (device globals — no allocation allowed)
// ---------------------------------------------------------------------------
__device__ float g_scores[BB * NN];
__device__ float g_u[BB * DD];
__device__ float g_C[BB];
__device__ float g_tau[BB];
__device__ float g_gbar[BB * DD];
__device__ __align__(16) unsigned long long g_wfrag[2048];
// precomposed matrices / vectors
__device__ float g_M1[DD * DD];    // M1[k,m] = sum_p wq2[k,p] wqp[p,m]
__device__ float g_A2t[DD * DD];   // A2t[m,i] = A2[i,m] = sum_j wx2[i,j] wkp[j,m]
__device__ float g_v[DD];          // v[m] = sum_i bx2[i] wkp[i,m] + bkp[m]
__device__ float g_cq[DD];         // cq[m] = sum_p bq2[p] wqp[p,m] + bqp[m]

__device__ __forceinline__ float gelu_exact(float x) {
    return 0.5f * x * (1.0f + erff(x * 0.7071067811865475f));
}

__device__ __forceinline__ void mma16816(float* c, const uint32_t* a,
                                         uint32_t b0, uint32_t b1) {
    asm volatile(
        "mma.sync.aligned.m16n8k16.row.col.f32.f16.f16.f32 "
        "{%0,%1,%2,%3}, {%4,%5,%6,%7}, {%8,%9}, {%0,%1,%2,%3};"
        : "+f"(c[0]), "+f"(c[1]), "+f"(c[2]), "+f"(c[3])
        : "r"(a[0]), "r"(a[1]), "r"(a[2]), "r"(a[3]), "r"(b0), "r"(b1));
}

__device__ __forceinline__ uint32_t pack_h2(float lo, float hi) {
    __half2 h = __floats2half2_rn(lo, hi);
    return *reinterpret_cast<uint32_t*>(&h);
}

// ---------------------------------------------------------------------------
// k1a: independent precomputes. 274 blocks x 128 threads.
// ---------------------------------------------------------------------------
__global__ void __launch_bounds__(128) k1a(
    const float* __restrict__ wx1,
    const float* __restrict__ wq2, const float* __restrict__ bq2,
    const float* __restrict__ wqp, const float* __restrict__ bqp,
    const float* __restrict__ wkp, const float* __restrict__ bkp,
    const float* __restrict__ wx2, const float* __restrict__ bx2)
{
    const int bid = blockIdx.x;
    const int t   = threadIdx.x;

    if (bid < 128) {                       // M1[k,m], k=bid, thread=m
        const int k = bid;
        float a0 = 0.f, a1 = 0.f;
#pragma unroll 8
        for (int p = 0; p < DD; p += 2) {
            a0 += wq2[k * DD + p + 0] * wqp[(p + 0) * DD + t];
            a1 += wq2[k * DD + p + 1] * wqp[(p + 1) * DD + t];
        }
        g_M1[k * DD + t] = a0 + a1;
    } else if (bid < 256) {                // A2[i,m], i=bid-128, thread=m
        const int i = bid - 128;
        float a0 = 0.f, a1 = 0.f;
#pragma unroll 8
        for (int j = 0; j < DD; j += 2) {
            a0 += wx2[i * DD + j + 0] * wkp[(j + 0) * DD + t];
            a1 += wx2[i * DD + j + 1] * wkp[(j + 1) * DD + t];
        }
        g_A2t[t * DD + i] = a0 + a1;       // transposed store
    } else if (bid < 272) {                // fp16 weight fragments for k2
        int s = (bid - 256) * 128 + t;     // 0..2047
        int l  = s & 31;
        int ks = (s >> 5) & 3;
        int nt = s >> 7;
        int n  = nt * 8 + (l >> 2);
        int k0 = ks * 16 + (l & 3) * 2;
        float w0 = wx1[(k0 + 0) * DD + n];
        float w1 = wx1[(k0 + 1) * DD + n];
        float w8 = wx1[(k0 + 8) * DD + n];
        float w9 = wx1[(k0 + 9) * DD + n];
        g_wfrag[s] = (unsigned long long)pack_h2(w0, w1)
                   | ((unsigned long long)pack_h2(w8, w9) << 32);
    } else if (bid == 272) {               // v[m]
        float a = 0.f;
#pragma unroll 8
        for (int i = 0; i < DD; i++) a += bx2[i] * wkp[i * DD + t];
        g_v[t] = a + bkp[t];
    } else {                               // cq[m]
        float a = 0.f;
#pragma unroll 8
        for (int p = 0; p < DD; p++) a += bq2[p] * wqp[p * DD + t];
        g_cq[t] = a + bqp[t];
    }
}

// ---------------------------------------------------------------------------
// k1c: per-batch finals. 32 blocks x 128.
//   qm = (g @ M1) + cq ;  u = A2 @ qm ;  C = qm . v
// ---------------------------------------------------------------------------
__global__ void __launch_bounds__(128) k1c(
    const float* __restrict__ xq_all,
    const float* __restrict__ wq1, const float* __restrict__ bq1)
{
    __shared__ float sg[DD];
    __shared__ float qm[DD];
    __shared__ float red[4];
    const int b = blockIdx.x;
    const int t = threadIdx.x;

    sg[t] = gelu_exact(xq_all[b] * wq1[t] + bq1[t]);
    __syncthreads();

    // qm[m] = sum_k sg[k] M1[k,m] + cq[m]
    {
        float a0 = 0.f, a1 = 0.f;
#pragma unroll 8
        for (int k = 0; k < DD; k += 2) {
            a0 += sg[k + 0] * g_M1[(k + 0) * DD + t];
            a1 += sg[k + 1] * g_M1[(k + 1) * DD + t];
        }
        qm[t] = a0 + a1 + g_cq[t];
    }
    __syncthreads();

    // u[i] = sum_m A2t[m,i] qm[m]
    {
        float a0 = 0.f, a1 = 0.f;
#pragma unroll 8
        for (int m = 0; m < DD; m += 2) {
            a0 += g_A2t[(m + 0) * DD + t] * qm[m + 0];
            a1 += g_A2t[(m + 1) * DD + t] * qm[m + 1];
        }
        g_u[b * DD + t] = a0 + a1;
    }

    // C = qm . v
    float p = qm[t] * g_v[t];
#pragma unroll
    for (int o = 16; o > 0; o >>= 1) p += __shfl_xor_sync(0xffffffffu, p, o);
    if ((t & 31) == 0) red[t >> 5] = p;
    __syncthreads();
    if (t == 0) g_C[b] = red[0] + red[1] + red[2] + red[3];
}

// ---------------------------------------------------------------------------
// Kernel 2 (dominant): single-product fp16 HMMA.
// Grid (NN/256, BB), 256 threads (8 warps). 256 items x 128 hidden, K=64.
// ---------------------------------------------------------------------------
static constexpr int S_B   = 0;         // 16384 bytes
static constexpr int S_US  = 16384;
static constexpr int S_BXS = S_US + 512;
static constexpr int S_TOT = S_BXS + 512;

__global__ void __launch_bounds__(256) k2_scores_hmma(
    const float* __restrict__ x_items,
    const float* __restrict__ bx1)
{
    extern __shared__ char smem[];
    const int tid = threadIdx.x;
    const int wid = tid >> 5;
    const int lid = tid & 31;
    const int qr  = lid >> 2;
    const int qc  = lid & 3;
    const int b   = blockIdx.y;
    const int tile0 = blockIdx.x * 256;

    float* us  = reinterpret_cast<float*>(smem + S_US);
    float* bxs = reinterpret_cast<float*>(smem + S_BXS);
    if (tid < DD) {
        us[tid]  = g_u[b * DD + tid];
        bxs[tid] = bx1[tid];
    }
    const float Cs = g_C[b];

    // ---- B: straight copy of prebuilt fragment buffer (16 KB)
    {
        const uint4* gf = reinterpret_cast<const uint4*>(g_wfrag);
        uint4* bs = reinterpret_cast<uint4*>(smem + S_B);
#pragma unroll
        for (int j = 0; j < 4; j++) bs[tid + j * 256] = gf[tid + j * 256];
    }

    // ---- A fragments: direct from global, fp16 pack
    uint32_t A[2][4][4];
    {
        const float* xb = x_items + ((size_t)b * NN + (size_t)tile0) * IDM;
#pragma unroll
        for (int mt = 0; mt < 2; mt++) {
            int r0 = wid * 32 + mt * 16 + qr;
#pragma unroll
            for (int ks = 0; ks < 4; ks++) {
                int k0 = ks * 16 + qc * 2;
                float2 v00 = *reinterpret_cast<const float2*>(xb + (size_t)r0 * IDM + k0);
                float2 v10 = *reinterpret_cast<const float2*>(xb + (size_t)(r0 + 8) * IDM + k0);
                float2 v01 = *reinterpret_cast<const float2*>(xb + (size_t)r0 * IDM + k0 + 8);
                float2 v11 = *reinterpret_cast<const float2*>(xb + (size_t)(r0 + 8) * IDM + k0 + 8);
                A[mt][ks][0] = pack_h2(v00.x, v00.y);
                A[mt][ks][1] = pack_h2(v10.x, v10.y);
                A[mt][ks][2] = pack_h2(v01.x, v01.y);
                A[mt][ks][3] = pack_h2(v11.x, v11.y);
            }
        }
    }
    __syncthreads();

    float sc[2][2] = {{0.f, 0.f}, {0.f, 0.f}};
#pragma unroll 1
    for (int nt = 0; nt < 16; nt++) {
        float c0[4] = {0.f, 0.f, 0.f, 0.f};
        float c1[4] = {0.f, 0.f, 0.f, 0.f};
#pragma unroll
        for (int ks = 0; ks < 4; ks++) {
            unsigned long long bb = *reinterpret_cast<const unsigned long long*>(
                smem + S_B + (((nt * 4 + ks) * 32) + lid) * 8);
            uint32_t b0 = (uint32_t)bb;
            uint32_t b1 = (uint32_t)(bb >> 32);
            mma16816(c0, A[0][ks], b0, b1);
            mma16816(c1, A[1][ks], b0, b1);
        }
        int n0 = nt * 8 + qc * 2;
        float2 bias = *reinterpret_cast<const float2*>(&bxs[n0]);
        float2 uu   = *reinterpret_cast<const float2*>(&us[n0]);
        sc[0][0] += gelu_exact(c0[0] + bias.x) * uu.x + gelu_exact(c0[1] + bias.y) * uu.y;
        sc[0][1] += gelu_exact(c0[2] + bias.x) * uu.x + gelu_exact(c0[3] + bias.y) * uu.y;
        sc[1][0] += gelu_exact(c1[0] + bias.x) * uu.x + gelu_exact(c1[1] + bias.y) * uu.y;
        sc[1][1] += gelu_exact(c1[2] + bias.x) * uu.x + gelu_exact(c1[3] + bias.y) * uu.y;
    }

#pragma unroll
    for (int mt = 0; mt < 2; mt++) {
#pragma unroll
        for (int h = 0; h < 2; h++) {
            float v = sc[mt][h];
            v += __shfl_xor_sync(0xffffffffu, v, 1);
            v += __shfl_xor_sync(0xffffffffu, v, 2);
            sc[mt][h] = v;
        }
    }
    if (qc == 0) {
#pragma unroll
        for (int mt = 0; mt < 2; mt++) {
#pragma unroll
            for (int h = 0; h < 2; h++) {
                int item = tile0 + wid * 32 + mt * 16 + h * 8 + qr;
                g_scores[b * NN + item] =
                    0.08838834764831845f * (sc[mt][h] + Cs);
            }
        }
    }
}

// ---------------------------------------------------------------------------
// k3a: tau via Michelot fixed point. 32 blocks x 1024. Also zeroes g_gbar.
// ---------------------------------------------------------------------------
#define MICH_ROUNDS 20

__global__ void __launch_bounds__(1024) k3a_tau()
{
    __shared__ float redS[MICH_ROUNDS];
    __shared__ float redK[MICH_ROUNDS];
    __shared__ float sM[32];

    const int tid  = threadIdx.x;
    const int b    = blockIdx.x;
    const int lane = tid & 31;
    const int wid  = tid >> 5;
    const float* sc = g_scores + b * NN;

    if (tid < MICH_ROUNDS) { redS[tid] = 0.f; redK[tid] = 0.f; }
    if (tid < DD) g_gbar[b * DD + tid] = 0.f;

    float z[16];
#pragma unroll
    for (int j = 0; j < 16; j++) z[j] = sc[tid + j * 1024];

    float m = z[0];
#pragma unroll
    for (int j = 1; j < 16; j++) m = fmaxf(m, z[j]);
#pragma unroll
    for (int o = 16; o > 0; o >>= 1) m = fmaxf(m, __shfl_xor_sync(0xffffffffu, m, o));
    if (lane == 0) sM[wid] = m;
    __syncthreads();
    float zmax = sM[0];
#pragma unroll
    for (int j = 1; j < 32; j++) zmax = fmaxf(zmax, sM[j]);

    float tau = zmax - 1.0f;
#pragma unroll 1
    for (int r = 0; r < MICH_ROUNDS; r++) {
        float s = 0.f, c = 0.f;
#pragma unroll
        for (int j = 0; j < 16; j++) {
            if (z[j] > tau) { s += z[j]; c += 1.f; }
        }
#pragma unroll
        for (int o = 16; o > 0; o >>= 1) {
            s += __shfl_xor_sync(0xffffffffu, s, o);
            c += __shfl_xor_sync(0xffffffffu, c, o);
        }
        if (lane == 0) {
            atomicAdd(&redS[r], s);
            atomicAdd(&redK[r], c);
        }
        __syncthreads();
        tau = (redS[r] - 1.0f) / redK[r];
    }

    if (tid == 0) g_tau[b] = tau;
}

// ---------------------------------------------------------------------------
// k3b: chunk-parallel sparse accumulation. Grid (16, 32) x 256 threads.
// Each block: 1024 items; each warp: 128 items (4 windows of 32).
// Gbar[b] += sum_{n in support} (z_n - tau) * gelu(x_n@wx1 + bx1)
// ---------------------------------------------------------------------------
__global__ void __launch_bounds__(256) k3b_accum(
    const float* __restrict__ x_items,
    const float* __restrict__ wx1, const float* __restrict__ bx1)
{
    __shared__ float accg[DD];
    const int tid  = threadIdx.x;
    const int lane = tid & 31;
    const int wid  = tid >> 5;
    const int b    = blockIdx.y;
    const int base = blockIdx.x * 1024 + wid * 128;

    if (tid < DD) accg[tid] = 0.f;
    __syncthreads();

    const float tau = g_tau[b];
    const float* sc = g_scores + b * NN;

#pragma unroll 1
    for (int win = 0; win < 4; win++) {
        int idx0 = base + win * 32;
        float zz = sc[idx0 + lane];
        unsigned msk = __ballot_sync(0xffffffffu, zz > tau);
        while (msk) {
            int jb = __ffs(msk) - 1;
            msk &= msk - 1;
            float w = __shfl_sync(0xffffffffu, zz, jb) - tau;
            int item = idx0 + jb;
            const float* xr = x_items + ((size_t)b * NN + (size_t)item) * IDM;
            float x0 = xr[2 * lane], x1 = xr[2 * lane + 1];
            float a0 = bx1[lane];
            float a1 = bx1[lane + 32];
            float a2 = bx1[lane + 64];
            float a3 = bx1[lane + 96];
#pragma unroll
            for (int k = 0; k < IDM; k++) {
                float xv = __shfl_sync(0xffffffffu, (k & 1) ? x1 : x0, k >> 1);
                a0 += xv * wx1[k * DD + lane];
                a1 += xv * wx1[k * DD + lane + 32];
                a2 += xv * wx1[k * DD + lane + 64];
                a3 += xv * wx1[k * DD + lane + 96];
            }
            atomicAdd(&accg[lane],      w * gelu_exact(a0));
            atomicAdd(&accg[lane + 32], w * gelu_exact(a1));
            atomicAdd(&accg[lane + 64], w * gelu_exact(a2));
            atomicAdd(&accg[lane + 96], w * gelu_exact(a3));
        }
    }
    __syncthreads();
    if (tid < DD) {
        float v = accg[tid];
        if (v != 0.f) atomicAdd(&g_gbar[b * DD + tid], v);
    }
}

// ---------------------------------------------------------------------------
// k3c: head MLP. 32 blocks x 128 threads.
// ---------------------------------------------------------------------------
__global__ void __launch_bounds__(128) k3c_head(
    const float* __restrict__ wx2, const float* __restrict__ bx2,
    const float* __restrict__ wvp, const float* __restrict__ bvp,
    const float* __restrict__ wp1, const float* __restrict__ bp1,
    const float* __restrict__ wp2, const float* __restrict__ bp2,
    float* __restrict__ out)
{
    __shared__ float accg[DD];
    __shared__ float buf1[DD];
    __shared__ float buf2[DD];
    const int b   = blockIdx.x;
    const int tid = threadIdx.x;

    accg[tid] = g_gbar[b * DD + tid];
    __syncthreads();

    {
        float a0 = 0.f, a1 = 0.f, a2 = 0.f, a3 = 0.f;
#pragma unroll 8
        for (int k = 0; k < DD; k += 4) {
            a0 += accg[k + 0] * wx2[(k + 0) * DD + tid];
            a1 += accg[k + 1] * wx2[(k + 1) * DD + tid];
            a2 += accg[k + 2] * wx2[(k + 2) * DD + tid];
            a3 += accg[k + 3] * wx2[(k + 3) * DD + tid];
        }
        buf1[tid] = (a0 + a1) + (a2 + a3) + bx2[tid];
    }
    __syncthreads();
    {
        float a0 = 0.f, a1 = 0.f, a2 = 0.f, a3 = 0.f;
#pragma unroll 8
        for (int k = 0; k < DD; k += 4) {
            a0 += buf1[k + 0] * wvp[(k + 0) * DD + tid];
            a1 += buf1[k + 1] * wvp[(k + 1) * DD + tid];
            a2 += buf1[k + 2] * wvp[(k + 2) * DD + tid];
            a3 += buf1[k + 3] * wvp[(k + 3) * DD + tid];
        }
        buf2[tid] = (a0 + a1) + (a2 + a3) + bvp[tid];
    }
    __syncthreads();
    {
        float a0 = 0.f, a1 = 0.f, a2 = 0.f, a3 = 0.f;
#pragma unroll 8
        for (int k = 0; k < DD; k += 4) {
            a0 += buf2[k + 0] * wp1[(k + 0) * DD + tid];
            a1 += buf2[k + 1] * wp1[(k + 1) * DD + tid];
            a2 += buf2[k + 2] * wp1[(k + 2) * DD + tid];
            a3 += buf2[k + 3] * wp1[(k + 3) * DD + tid];
        }
        buf1[tid] = gelu_exact((a0 + a1) + (a2 + a3) + bp1[tid]);
    }
    __syncthreads();
    if (tid < NCLS) {
        float o = bp2[tid];
#pragma unroll 8
        for (int k = 0; k < DD; k++) o += buf1[k] * wp2[k * NCLS + tid];
        out[b * NCLS + tid] = o;
    }
}

// ---------------------------------------------------------------------------
extern "C" void kernel_launch(void* const* d_in, const int* in_sizes, int n_in,
                              void* d_out, int out_size)
{
    const float* x_items = (const float*)d_in[0];
    const float* x_query = (const float*)d_in[1];
    const float* wx1 = (const float*)d_in[2];
    const float* bx1 = (const float*)d_in[3];
    const float* wx2 = (const float*)d_in[4];
    const float* bx2 = (const float*)d_in[5];
    const float* wq1 = (const float*)d_in[6];
    const float* bq1 = (const float*)d_in[7];
    const float* wq2 = (const float*)d_in[8];
    const float* bq2 = (const float*)d_in[9];
    const float* wqp = (const float*)d_in[10];
    const float* bqp = (const float*)d_in[11];
    const float* wkp = (const float*)d_in[12];
    const float* bkp = (const float*)d_in[13];
    const float* wvp = (const float*)d_in[14];
    const float* bvp = (const float*)d_in[15];
    const float* wp1 = (const float*)d_in[16];
    const float* bp1 = (const float*)d_in[17];
    const float* wp2 = (const float*)d_in[18];
    const float* bp2 = (const float*)d_in[19];
    float* out = (float*)d_out;

    cudaFuncSetAttribute(k2_scores_hmma,
                         cudaFuncAttributeMaxDynamicSharedMemorySize, S_TOT);

    k1a<<<274, 128>>>(wx1, wq2, bq2, wqp, bqp, wkp, bkp, wx2, bx2);
    k1c<<<BB, 128>>>(x_query, wq1, bq1);

    dim3 g2(NN / 256, BB);
    k2_scores_hmma<<<g2, 256, S_TOT>>>(x_items, bx1);

    k3a_tau<<<BB, 1024>>>();
    dim3 g3(16, BB);
    k3b_accum<<<g3, 256>>>(x_items, wx1, bx1);
    k3c_head<<<BB, 128>>>(wx2, bx2, wvp, bvp, wp1, bp1, wp2, bp2, out);
}

// round 12
// speedup vs baseline: 3.4871x; 1.2862x over previous
#include <cuda_runtime.h>
#include <cuda_fp16.h>
#include <cstdint>

#define BB   32
#define NN   16384
#define DD   128
#define IDM  64
#define NCLS 10

// ---------------------------------------------------------------------------
// Scratch (device globals — no allocation allowed)
// ---------------------------------------------------------------------------
__device__ float g_scores[BB * NN];
__device__ float g_u[BB * DD];
__device__ float g_C[BB];
__device__ float g_tau[BB];
__device__ float g_gbar[BB * DD];
__device__ __align__(16) unsigned long long g_wfrag[2048];
__device__ float g_M1[DD * DD];    // M1[k,m] = sum_p wq2[k,p] wqp[p,m]
__device__ float g_A2t[DD * DD];   // A2t[m,i] = sum_j wx2[i,j] wkp[j,m]
__device__ float g_v[DD];          // v[m] = sum_i bx2[i] wkp[i,m] + bkp[m]
__device__ float g_cq[DD];         // cq[m] = sum_p bq2[p] wqp[p,m] + bqp[m]

__device__ __forceinline__ float gelu_exact(float x) {
    return 0.5f * x * (1.0f + erff(x * 0.7071067811865475f));
}

// tanh-form gelu via sigmoid: 0.5x(1+tanh(y)) = x * sigmoid(2y)
__device__ __forceinline__ float gelu_fast(float x) {
    float y2 = 1.5957691216057308f * x * fmaf(0.044715f, x * x, 1.0f); // 2y
    float e = __expf(-y2);
    return x * __fdividef(1.0f, 1.0f + e);
}

__device__ __forceinline__ void mma16816(float* c, const uint32_t* a,
                                         uint32_t b0, uint32_t b1) {
    asm volatile(
        "mma.sync.aligned.m16n8k16.row.col.f32.f16.f16.f32 "
        "{%0,%1,%2,%3}, {%4,%5,%6,%7}, {%8,%9}, {%0,%1,%2,%3};"
        : "+f"(c[0]), "+f"(c[1]), "+f"(c[2]), "+f"(c[3])
        : "r"(a[0]), "r"(a[1]), "r"(a[2]), "r"(a[3]), "r"(b0), "r"(b1));
}

__device__ __forceinline__ uint32_t pack_h2(float lo, float hi) {
    __half2 h = __floats2half2_rn(lo, hi);
    return *reinterpret_cast<uint32_t*>(&h);
}

// ---------------------------------------------------------------------------
// k1a: independent precomputes. 274 blocks x 128 threads.
// ---------------------------------------------------------------------------
__global__ void __launch_bounds__(128) k1a(
    const float* __restrict__ wx1,
    const float* __restrict__ wq2, const float* __restrict__ bq2,
    const float* __restrict__ wqp, const float* __restrict__ bqp,
    const float* __restrict__ wkp, const float* __restrict__ bkp,
    const float* __restrict__ wx2, const float* __restrict__ bx2)
{
    const int bid = blockIdx.x;
    const int t   = threadIdx.x;

    if (bid < 128) {                       // M1[k,m]
        const int k = bid;
        float a0 = 0.f, a1 = 0.f;
#pragma unroll 8
        for (int p = 0; p < DD; p += 2) {
            a0 += wq2[k * DD + p + 0] * wqp[(p + 0) * DD + t];
            a1 += wq2[k * DD + p + 1] * wqp[(p + 1) * DD + t];
        }
        g_M1[k * DD + t] = a0 + a1;
    } else if (bid < 256) {                // A2[i,m] stored transposed
        const int i = bid - 128;
        float a0 = 0.f, a1 = 0.f;
#pragma unroll 8
        for (int j = 0; j < DD; j += 2) {
            a0 += wx2[i * DD + j + 0] * wkp[(j + 0) * DD + t];
            a1 += wx2[i * DD + j + 1] * wkp[(j + 1) * DD + t];
        }
        g_A2t[t * DD + i] = a0 + a1;
    } else if (bid < 272) {                // fp16 weight fragments for k2
        int s = (bid - 256) * 128 + t;
        int l  = s & 31;
        int ks = (s >> 5) & 3;
        int nt = s >> 7;
        int n  = nt * 8 + (l >> 2);
        int k0 = ks * 16 + (l & 3) * 2;
        float w0 = wx1[(k0 + 0) * DD + n];
        float w1 = wx1[(k0 + 1) * DD + n];
        float w8 = wx1[(k0 + 8) * DD + n];
        float w9 = wx1[(k0 + 9) * DD + n];
        g_wfrag[s] = (unsigned long long)pack_h2(w0, w1)
                   | ((unsigned long long)pack_h2(w8, w9) << 32);
    } else if (bid == 272) {               // v[m]
        float a = 0.f;
#pragma unroll 8
        for (int i = 0; i < DD; i++) a += bx2[i] * wkp[i * DD + t];
        g_v[t] = a + bkp[t];
    } else {                               // cq[m]
        float a = 0.f;
#pragma unroll 8
        for (int p = 0; p < DD; p++) a += bq2[p] * wqp[p * DD + t];
        g_cq[t] = a + bqp[t];
    }
}

// ---------------------------------------------------------------------------
// k1c: per-batch finals. 32 blocks x 128.
// ---------------------------------------------------------------------------
__global__ void __launch_bounds__(128) k1c(
    const float* __restrict__ xq_all,
    const float* __restrict__ wq1, const float* __restrict__ bq1)
{
    __shared__ float sg[DD];
    __shared__ float qm[DD];
    __shared__ float red[4];
    const int b = blockIdx.x;
    const int t = threadIdx.x;

    sg[t] = gelu_exact(xq_all[b] * wq1[t] + bq1[t]);
    __syncthreads();

    {
        float a0 = 0.f, a1 = 0.f;
#pragma unroll 8
        for (int k = 0; k < DD; k += 2) {
            a0 += sg[k + 0] * g_M1[(k + 0) * DD + t];
            a1 += sg[k + 1] * g_M1[(k + 1) * DD + t];
        }
        qm[t] = a0 + a1 + g_cq[t];
    }
    __syncthreads();

    {
        float a0 = 0.f, a1 = 0.f;
#pragma unroll 8
        for (int m = 0; m < DD; m += 2) {
            a0 += g_A2t[(m + 0) * DD + t] * qm[m + 0];
            a1 += g_A2t[(m + 1) * DD + t] * qm[m + 1];
        }
        g_u[b * DD + t] = a0 + a1;
    }

    float p = qm[t] * g_v[t];
#pragma unroll
    for (int o = 16; o > 0; o >>= 1) p += __shfl_xor_sync(0xffffffffu, p, o);
    if ((t & 31) == 0) red[t >> 5] = p;
    __syncthreads();
    if (t == 0) g_C[b] = red[0] + red[1] + red[2] + red[3];
}

// ---------------------------------------------------------------------------
// Kernel 2 (dominant): single-product fp16 HMMA + fast gelu epilogue.
// Grid (NN/256, BB), 256 threads (8 warps).
// ---------------------------------------------------------------------------
static constexpr int S_B   = 0;         // 16384 bytes
static constexpr int S_US  = 16384;
static constexpr int S_BXS = S_US + 512;
static constexpr int S_TOT = S_BXS + 512;

__global__ void __launch_bounds__(256) k2_scores_hmma(
    const float* __restrict__ x_items,
    const float* __restrict__ bx1)
{
    extern __shared__ char smem[];
    const int tid = threadIdx.x;
    const int wid = tid >> 5;
    const int lid = tid & 31;
    const int qr  = lid >> 2;
    const int qc  = lid & 3;
    const int b   = blockIdx.y;
    const int tile0 = blockIdx.x * 256;

    float* us  = reinterpret_cast<float*>(smem + S_US);
    float* bxs = reinterpret_cast<float*>(smem + S_BXS);
    if (tid < DD) {
        us[tid]  = g_u[b * DD + tid];
        bxs[tid] = bx1[tid];
    }
    const float Cs = g_C[b];

    {
        const uint4* gf = reinterpret_cast<const uint4*>(g_wfrag);
        uint4* bs = reinterpret_cast<uint4*>(smem + S_B);
#pragma unroll
        for (int j = 0; j < 4; j++) bs[tid + j * 256] = gf[tid + j * 256];
    }

    uint32_t A[2][4][4];
    {
        const float* xb = x_items + ((size_t)b * NN + (size_t)tile0) * IDM;
#pragma unroll
        for (int mt = 0; mt < 2; mt++) {
            int r0 = wid * 32 + mt * 16 + qr;
#pragma unroll
            for (int ks = 0; ks < 4; ks++) {
                int k0 = ks * 16 + qc * 2;
                float2 v00 = *reinterpret_cast<const float2*>(xb + (size_t)r0 * IDM + k0);
                float2 v10 = *reinterpret_cast<const float2*>(xb + (size_t)(r0 + 8) * IDM + k0);
                float2 v01 = *reinterpret_cast<const float2*>(xb + (size_t)r0 * IDM + k0 + 8);
                float2 v11 = *reinterpret_cast<const float2*>(xb + (size_t)(r0 + 8) * IDM + k0 + 8);
                A[mt][ks][0] = pack_h2(v00.x, v00.y);
                A[mt][ks][1] = pack_h2(v10.x, v10.y);
                A[mt][ks][2] = pack_h2(v01.x, v01.y);
                A[mt][ks][3] = pack_h2(v11.x, v11.y);
            }
        }
    }
    __syncthreads();

    float sc[2][2] = {{0.f, 0.f}, {0.f, 0.f}};
#pragma unroll 1
    for (int nt = 0; nt < 16; nt++) {
        float c0[4] = {0.f, 0.f, 0.f, 0.f};
        float c1[4] = {0.f, 0.f, 0.f, 0.f};
#pragma unroll
        for (int ks = 0; ks < 4; ks++) {
            unsigned long long bb = *reinterpret_cast<const unsigned long long*>(
                smem + S_B + (((nt * 4 + ks) * 32) + lid) * 8);
            uint32_t b0 = (uint32_t)bb;
            uint32_t b1 = (uint32_t)(bb >> 32);
            mma16816(c0, A[0][ks], b0, b1);
            mma16816(c1, A[1][ks], b0, b1);
        }
        int n0 = nt * 8 + qc * 2;
        float2 bias = *reinterpret_cast<const float2*>(&bxs[n0]);
        float2 uu   = *reinterpret_cast<const float2*>(&us[n0]);
        sc[0][0] += gelu_fast(c0[0] + bias.x) * uu.x + gelu_fast(c0[1] + bias.y) * uu.y;
        sc[0][1] += gelu_fast(c0[2] + bias.x) * uu.x + gelu_fast(c0[3] + bias.y) * uu.y;
        sc[1][0] += gelu_fast(c1[0] + bias.x) * uu.x + gelu_fast(c1[1] + bias.y) * uu.y;
        sc[1][1] += gelu_fast(c1[2] + bias.x) * uu.x + gelu_fast(c1[3] + bias.y) * uu.y;
    }

#pragma unroll
    for (int mt = 0; mt < 2; mt++) {
#pragma unroll
        for (int h = 0; h < 2; h++) {
            float v = sc[mt][h];
            v += __shfl_xor_sync(0xffffffffu, v, 1);
            v += __shfl_xor_sync(0xffffffffu, v, 2);
            sc[mt][h] = v;
        }
    }
    if (qc == 0) {
#pragma unroll
        for (int mt = 0; mt < 2; mt++) {
#pragma unroll
            for (int h = 0; h < 2; h++) {
                int item = tile0 + wid * 32 + mt * 16 + h * 8 + qr;
                g_scores[b * NN + item] =
                    0.08838834764831845f * (sc[mt][h] + Cs);
            }
        }
    }
}

// ---------------------------------------------------------------------------
// k3a: tau via Michelot fixed point, atomic-free double-buffered reduction,
// uniform early exit. 32 blocks x 1024. Also zeroes g_gbar.
// ---------------------------------------------------------------------------
#define MICH_ROUNDS 20

__global__ void __launch_bounds__(1024) k3a_tau()
{
    __shared__ float sS[2][32];
    __shared__ float sK[2][32];
    __shared__ float sM[32];

    const int tid  = threadIdx.x;
    const int b    = blockIdx.x;
    const int lane = tid & 31;
    const int wid  = tid >> 5;
    const float* sc = g_scores + b * NN;

    if (tid < DD) g_gbar[b * DD + tid] = 0.f;

    float z[16];
#pragma unroll
    for (int j = 0; j < 16; j++) z[j] = sc[tid + j * 1024];

    // block max: warp reduce -> slot -> everyone sums 32 (1 barrier)
    float m = z[0];
#pragma unroll
    for (int j = 1; j < 16; j++) m = fmaxf(m, z[j]);
#pragma unroll
    for (int o = 16; o > 0; o >>= 1) m = fmaxf(m, __shfl_xor_sync(0xffffffffu, m, o));
    if (lane == 0) sM[wid] = m;
    __syncthreads();
    float zmax = sM[0];
#pragma unroll
    for (int j = 1; j < 32; j++) zmax = fmaxf(zmax, sM[j]);

    // Michelot: tau <- (sum_{z>tau} z - 1)/count; fixed point = (S-1)/k exact.
    float tau = zmax - 1.0f;
#pragma unroll 1
    for (int r = 0; r < MICH_ROUNDS; r++) {
        float s = 0.f, c = 0.f;
#pragma unroll
        for (int j = 0; j < 16; j++) {
            if (z[j] > tau) { s += z[j]; c += 1.f; }
        }
#pragma unroll
        for (int o = 16; o > 0; o >>= 1) {
            s += __shfl_xor_sync(0xffffffffu, s, o);
            c += __shfl_xor_sync(0xffffffffu, c, o);
        }
        const int p = r & 1;
        if (lane == 0) { sS[p][wid] = s; sK[p][wid] = c; }
        __syncthreads();
        float S = 0.f, K = 0.f;
#pragma unroll
        for (int j = 0; j < 32; j++) { S += sS[p][j]; K += sK[p][j]; }
        float tn = (S - 1.0f) / K;        // identical in all threads
        if (tn == tau) break;             // uniform exit
        tau = tn;
    }

    if (tid == 0) g_tau[b] = tau;
}

// ---------------------------------------------------------------------------
// k3b: chunk-parallel sparse accumulation. Grid (32, 32) x 256 threads.
// Each block: 512 items; each warp: 64 items (2 windows of 32).
// ---------------------------------------------------------------------------
__global__ void __launch_bounds__(256) k3b_accum(
    const float* __restrict__ x_items,
    const float* __restrict__ wx1, const float* __restrict__ bx1)
{
    __shared__ float accg[DD];
    const int tid  = threadIdx.x;
    const int lane = tid & 31;
    const int wid  = tid >> 5;
    const int b    = blockIdx.y;
    const int base = blockIdx.x * 512 + wid * 64;

    if (tid < DD) accg[tid] = 0.f;
    __syncthreads();

    const float tau = g_tau[b];
    const float* sc = g_scores + b * NN;

#pragma unroll 1
    for (int win = 0; win < 2; win++) {
        int idx0 = base + win * 32;
        float zz = sc[idx0 + lane];
        unsigned msk = __ballot_sync(0xffffffffu, zz > tau);
        while (msk) {
            int jb = __ffs(msk) - 1;
            msk &= msk - 1;
            float w = __shfl_sync(0xffffffffu, zz, jb) - tau;
            int item = idx0 + jb;
            const float* xr = x_items + ((size_t)b * NN + (size_t)item) * IDM;
            float x0 = xr[2 * lane], x1 = xr[2 * lane + 1];
            float a0 = bx1[lane];
            float a1 = bx1[lane + 32];
            float a2 = bx1[lane + 64];
            float a3 = bx1[lane + 96];
#pragma unroll
            for (int k = 0; k < IDM; k++) {
                float xv = __shfl_sync(0xffffffffu, (k & 1) ? x1 : x0, k >> 1);
                a0 += xv * wx1[k * DD + lane];
                a1 += xv * wx1[k * DD + lane + 32];
                a2 += xv * wx1[k * DD + lane + 64];
                a3 += xv * wx1[k * DD + lane + 96];
            }
            atomicAdd(&accg[lane],      w * gelu_exact(a0));
            atomicAdd(&accg[lane + 32], w * gelu_exact(a1));
            atomicAdd(&accg[lane + 64], w * gelu_exact(a2));
            atomicAdd(&accg[lane + 96], w * gelu_exact(a3));
        }
    }
    __syncthreads();
    if (tid < DD) {
        float v = accg[tid];
        if (v != 0.f) atomicAdd(&g_gbar[b * DD + tid], v);
    }
}

// ---------------------------------------------------------------------------
// k3c: head MLP. 32 blocks x 128 threads.
// ---------------------------------------------------------------------------
__global__ void __launch_bounds__(128) k3c_head(
    const float* __restrict__ wx2, const float* __restrict__ bx2,
    const float* __restrict__ wvp, const float* __restrict__ bvp,
    const float* __restrict__ wp1, const float* __restrict__ bp1,
    const float* __restrict__ wp2, const float* __restrict__ bp2,
    float* __restrict__ out)
{
    __shared__ float accg[DD];
    __shared__ float buf1[DD];
    __shared__ float buf2[DD];
    const int b   = blockIdx.x;
    const int tid = threadIdx.x;

    accg[tid] = g_gbar[b * DD + tid];
    __syncthreads();

    {
        float a0 = 0.f, a1 = 0.f, a2 = 0.f, a3 = 0.f;
#pragma unroll 8
        for (int k = 0; k < DD; k += 4) {
            a0 += accg[k + 0] * wx2[(k + 0) * DD + tid];
            a1 += accg[k + 1] * wx2[(k + 1) * DD + tid];
            a2 += accg[k + 2] * wx2[(k + 2) * DD + tid];
            a3 += accg[k + 3] * wx2[(k + 3) * DD + tid];
        }
        buf1[tid] = (a0 + a1) + (a2 + a3) + bx2[tid];
    }
    __syncthreads();
    {
        float a0 = 0.f, a1 = 0.f, a2 = 0.f, a3 = 0.f;
#pragma unroll 8
        for (int k = 0; k < DD; k += 4) {
            a0 += buf1[k + 0] * wvp[(k + 0) * DD + tid];
            a1 += buf1[k + 1] * wvp[(k + 1) * DD + tid];
            a2 += buf1[k + 2] * wvp[(k + 2) * DD + tid];
            a3 += buf1[k + 3] * wvp[(k + 3) * DD + tid];
        }
        buf2[tid] = (a0 + a1) + (a2 + a3) + bvp[tid];
    }
    __syncthreads();
    {
        float a0 = 0.f, a1 = 0.f, a2 = 0.f, a3 = 0.f;
#pragma unroll 8
        for (int k = 0; k < DD; k += 4) {
            a0 += buf2[k + 0] * wp1[(k + 0) * DD + tid];
            a1 += buf2[k + 1] * wp1[(k + 1) * DD + tid];
            a2 += buf2[k + 2] * wp1[(k + 2) * DD + tid];
            a3 += buf2[k + 3] * wp1[(k + 3) * DD + tid];
        }
        buf1[tid] = gelu_exact((a0 + a1) + (a2 + a3) + bp1[tid]);
    }
    __syncthreads();
    if (tid < NCLS) {
        float o = bp2[tid];
#pragma unroll 8
        for (int k = 0; k < DD; k++) o += buf1[k] * wp2[k * NCLS + tid];
        out[b * NCLS + tid] = o;
    }
}

// ---------------------------------------------------------------------------
extern "C" void kernel_launch(void* const* d_in, const int* in_sizes, int n_in,
                              void* d_out, int out_size)
{
    const float* x_items = (const float*)d_in[0];
    const float* x_query = (const float*)d_in[1];
    const float* wx1 = (const float*)d_in[2];
    const float* bx1 = (const float*)d_in[3];
    const float* wx2 = (const float*)d_in[4];
    const float* bx2 = (const float*)d_in[5];
    const float* wq1 = (const float*)d_in[6];
    const float* bq1 = (const float*)d_in[7];
    const float* wq2 = (const float*)d_in[8];
    const float* bq2 = (const float*)d_in[9];
    const float* wqp = (const float*)d_in[10];
    const float* bqp = (const float*)d_in[11];
    const float* wkp = (const float*)d_in[12];
    const float* bkp = (const float*)d_in[13];
    const float* wvp = (const float*)d_in[14];
    const float* bvp = (const float*)d_in[15];
    const float* wp1 = (const float*)d_in[16];
    const float* bp1 = (const float*)d_in[17];
    const float* wp2 = (const float*)d_in[18];
    const float* bp2 = (const float*)d_in[19];
    float* out = (float*)d_out;

    cudaFuncSetAttribute(k2_scores_hmma,
                         cudaFuncAttributeMaxDynamicSharedMemorySize, S_TOT);

    k1a<<<274, 128>>>(wx1, wq2, bq2, wqp, bqp, wkp, bkp, wx2, bx2);
    k1c<<<BB, 128>>>(x_query, wq1, bq1);

    dim3 g2(NN / 256, BB);
    k2_scores_hmma<<<g2, 256, S_TOT>>>(x_items, bx1);

    k3a_tau<<<BB, 1024>>>();
    dim3 g3(32, BB);
    k3b_accum<<<g3, 256>>>(x_items, wx1, bx1);
    k3c_head<<<BB, 128>>>(wx2, bx2, wvp, bvp, wp1, bp1, wp2, bp2, out);
}